// round 12
// baseline (speedup 1.0000x reference)
#include <cuda_runtime.h>
#include <cuda_fp16.h>
#include <cstdint>

#define NN 100000
#define NE 400000
#define NG 1000
#define EPSV 1e-5f

__device__ __half g_P[(size_t)NN * 256];
__device__ __half g_Q[(size_t)NN * 256];
__device__ __half g_h1[(size_t)NN * 128];
__device__ __half g_h2[(size_t)NN * 256];
__device__ __half g_h3[(size_t)NN * 256];
__device__ __half g_e0[(size_t)NE * 256];
__device__ __half g_e1[(size_t)NE * 128];
__device__ int    g_src[NE];
__device__ int    g_dst[NE];
__device__ int    g_ssrc[NE];
__device__ int    g_sdst[NE];
__device__ int    g_batch[NN];
__device__ int    g_hist[NN];
__device__ int    g_dout[NN];
__device__ int    g_seg[NN + 1];
__device__ int    g_cur[NN];
__device__ int    g_ghist[NG];
__device__ int    g_gseg[NG + 1];
__device__ float  g_invdeg[NN];
__device__ double g_sum[256];
__device__ double g_sumsq[256];
__device__ float  g_alpha[256];
__device__ float  g_beta[256];
__device__ uint32_t g_wtp [2 * 8 * 2048];
__device__ uint32_t g_wtpA[2 * 8 * 2048];
__device__ uint32_t g_wtpB[2 * 8 * 2048];
__device__ float  g_pool[NG * 256];

__device__ __forceinline__ uint32_t h2u(__half2 h) { return *reinterpret_cast<uint32_t*>(&h); }
__device__ __forceinline__ __half2 u2h(uint32_t u) { return *reinterpret_cast<__half2*>(&u); }
__device__ __forceinline__ float2 uf2(uint32_t u) { return __half22float2(u2h(u)); }

__device__ __forceinline__ uint32_t aff2(uint32_t u, float ax, float ay, float bx, float by) {
    float2 f = uf2(u);
    return h2u(__floats2half2_rn(fmaxf(fmaf(ax, f.x, bx), 0.f),
                                 fmaxf(fmaf(ay, f.y, by), 0.f)));
}
__device__ __forceinline__ uint32_t aff2s(uint32_t up, uint32_t uq,
                                          float ax, float ay, float bx, float by) {
    float2 p = uf2(up), q = uf2(uq);
    return h2u(__floats2half2_rn(fmaxf(fmaf(ax, p.x + q.x, bx), 0.f),
                                 fmaxf(fmaf(ay, p.y + q.y, by), 0.f)));
}

// ---------------- convert + histograms ----------------
__global__ void k_convert(const void* __restrict__ ei, const void* __restrict__ bt) {
    __shared__ int s64;
    if (threadIdx.x == 0) {
        const unsigned long long* e = (const unsigned long long*)ei;
        int f = 1;
        for (int i = 0; i < 256; i++)
            if (e[i] >= (unsigned long long)NN) { f = 0; break; }
        s64 = f;
    }
    __syncthreads();
    const int is64 = s64;
    int i0 = blockIdx.x * blockDim.x + threadIdx.x;
    int st = gridDim.x * blockDim.x;
    for (int k = i0; k < NE; k += st) {
        int s, d;
        if (is64) {
            const long long* e = (const long long*)ei;
            s = (int)e[k]; d = (int)e[NE + k];
        } else {
            const int* e = (const int*)ei;
            s = e[k]; d = e[NE + k];
        }
        g_src[k] = s; g_dst[k] = d;
        atomicAdd(&g_hist[d], 1);
        atomicAdd(&g_dout[s], 1);
    }
    for (int k = i0; k < NN; k += st) {
        int b = is64 ? (int)((const long long*)bt)[k] : ((const int*)bt)[k];
        g_batch[k] = b;
        atomicAdd(&g_ghist[b], 1);
    }
}

__global__ void k_scan_nodes() {
    __shared__ int wsum[32];
    __shared__ int carry;
    int t = threadIdx.x, lane = t & 31, wid = t >> 5;
    if (t == 0) carry = 0;
    __syncthreads();
    for (int base = 0; base < NN; base += 1024) {
        int i = base + t;
        int v = (i < NN) ? g_hist[i] : 0;
        int x = v;
#pragma unroll
        for (int off = 1; off < 32; off <<= 1) {
            int y = __shfl_up_sync(0xFFFFFFFFu, x, off);
            if (lane >= off) x += y;
        }
        if (lane == 31) wsum[wid] = x;
        __syncthreads();
        if (wid == 0) {
            int wv = wsum[lane];
#pragma unroll
            for (int off = 1; off < 32; off <<= 1) {
                int y = __shfl_up_sync(0xFFFFFFFFu, wv, off);
                if (lane >= off) wv += y;
            }
            wsum[lane] = wv;
        }
        __syncthreads();
        int incl = x + (wid ? wsum[wid - 1] : 0);
        int c = carry;
        if (i < NN) {
            g_seg[i] = c + incl - v;
            g_cur[i] = c + incl - v;
            g_invdeg[i] = 1.f / fmaxf((float)v, 1.f);
        }
        __syncthreads();
        if (t == 1023) carry += incl;
        __syncthreads();
    }
    if (t == 0) g_seg[NN] = carry;
}

__global__ void k_scan_graphs() {
    __shared__ int sb[1024];
    int t = threadIdx.x;
    int v = (t < NG) ? g_ghist[t] : 0;
    sb[t] = v;
    __syncthreads();
    for (int off = 1; off < 1024; off <<= 1) {
        int x = sb[t];
        int y = (t >= off) ? sb[t - off] : 0;
        __syncthreads();
        sb[t] = x + y;
        __syncthreads();
    }
    if (t < NG) g_gseg[t] = sb[t] - v;
    if (t == 1023) g_gseg[NG] = sb[1023];
}

__global__ void k_scatter() {
    int i = blockIdx.x * blockDim.x + threadIdx.x;
    for (; i < NE; i += gridDim.x * blockDim.x) {
        int d = g_dst[i];
        int p = atomicAdd(&g_cur[d], 1);
        g_ssrc[p] = g_src[i];
        g_sdst[p] = d;
    }
}

// layer-1 of block 1 + fused node-term stats (din*p+dout*q, din*p^2+dout*q^2)
__global__ void k_l1(const float* __restrict__ x, const float* __restrict__ W) {
    __shared__ float wd[5 * 128], wb[5 * 128];
    int c = threadIdx.x;
#pragma unroll
    for (int k = 0; k < 5; k++) {
        float t = W[(5 + k) * 128 + c];
        wb[k * 128 + c] = t;
        wd[k * 128 + c] = W[k * 128 + c] - t;
    }
    __syncthreads();
    float sacc = 0.f, qacc = 0.f;
    for (int n = blockIdx.x; n < NN; n += gridDim.x) {
        float xv[5];
#pragma unroll
        for (int k = 0; k < 5; k++) xv[k] = x[n * 5 + k];
        float p = 0.f, q = 0.f;
#pragma unroll
        for (int k = 0; k < 5; k++) {
            p = fmaf(xv[k], wd[k * 128 + c], p);
            q = fmaf(xv[k], wb[k * 128 + c], q);
        }
        g_P[(size_t)n * 128 + c] = __float2half_rn(p);
        g_Q[(size_t)n * 128 + c] = __float2half_rn(q);
        // half-rounded values enter edges; use rounded for stats consistency
        float ph = __half2float(__float2half_rn(p));
        float qh = __half2float(__float2half_rn(q));
        float din = (float)(g_seg[n + 1] - g_seg[n]);
        float dou = (float)g_dout[n];
        sacc += din * ph + dou * qh;
        qacc += din * ph * ph + dou * qh * qh;
    }
    atomicAdd(&g_sum[c], (double)sacc);
    atomicAdd(&g_sumsq[c], (double)qacc);
}

// ---- cross-term stats only: g_sumsq += 2 * sum_n P[n] . R[n], R = seg-gather of Q ----
__global__ void k_cross(const __half* __restrict__ P, const __half* __restrict__ Qb, int logC) {
    __shared__ float Sq[256];
    const int opn = 1 << (logC - 3);
    const int t = threadIdx.x;
    const int nlane = t >> (logC - 3);
    const int npb = 256 >> (logC - 3);
    const int cc = (t & (opn - 1)) << 3;
    if (t < (1 << logC)) Sq[t] = 0.f;

    float q[8];
#pragma unroll
    for (int i = 0; i < 8; i++) q[i] = 0.f;

    const int ngroups = (NN + npb - 1) / npb;
    for (int ng = blockIdx.x; ng < ngroups; ng += gridDim.x) {
        int n = ng * npb + nlane;
        if (n >= NN) continue;
        int p0 = g_seg[n], p1 = g_seg[n + 1];
        if (p0 == p1) continue;
        float r[8];
#pragma unroll
        for (int i = 0; i < 8; i++) r[i] = 0.f;
        for (int p = p0; p < p1; p++) {
            int sidx = g_ssrc[p];
            uint4 sv = *(const uint4*)(Qb + ((size_t)sidx << logC) + cc);
            float2 a;
            a = uf2(sv.x); r[0] += a.x; r[1] += a.y;
            a = uf2(sv.y); r[2] += a.x; r[3] += a.y;
            a = uf2(sv.z); r[4] += a.x; r[5] += a.y;
            a = uf2(sv.w); r[6] += a.x; r[7] += a.y;
        }
        uint4 pv = *(const uint4*)(P + ((size_t)n << logC) + cc);
        float2 a;
        a = uf2(pv.x); q[0] += a.x * r[0]; q[1] += a.y * r[1];
        a = uf2(pv.y); q[2] += a.x * r[2]; q[3] += a.y * r[3];
        a = uf2(pv.z); q[4] += a.x * r[4]; q[5] += a.y * r[5];
        a = uf2(pv.w); q[6] += a.x * r[6]; q[7] += a.y * r[7];
    }
    __syncthreads();
#pragma unroll
    for (int i = 0; i < 8; i++) atomicAdd(&Sq[cc + i], 2.f * q[i]);
    __syncthreads();
    if (t < (1 << logC)) atomicAdd(&g_sumsq[t], (double)Sq[t]);
}

__global__ void k_finalize(const float* __restrict__ gn, int C, const float* __restrict__ comb) {
    int c = threadIdx.x;
    if (c < C) {
        double s = g_sum[c], q = g_sumsq[c];
        if (comb) {
            double bc = (double)comb[c];
            q += 2.0 * bc * s + (double)NE * bc * bc;
            s += (double)NE * bc;
        }
        float invE = 1.f / (float)NE;
        float m  = (float)(s * invE);
        float m2 = (float)(q * invE);
        float g = gn[c], b = gn[C + c], ms = gn[2 * C + c];
        float var = m2 - 2.f * ms * m * m + ms * ms * m * m;
        float rs = rsqrtf(var + EPSV);
        g_alpha[c] = g * rs;
        g_beta[c]  = b - g * rs * ms * m;
        g_sum[c] = 0.0;
        g_sumsq[c] = 0.0;
    }
}

// pre-permute weights into mma B-fragment layout
__global__ void k_trp(const float* __restrict__ Wa, const float* __restrict__ Wb,
                      uint32_t* __restrict__ out, int K, int N) {
    int tot = N * (K >> 1);
    int i = blockIdx.x * blockDim.x + threadIdx.x;
    for (; i < tot; i += gridDim.x * blockDim.x) {
        int n = i / (K >> 1);
        int kp = i - n * (K >> 1);
        int k = kp << 1;
        float v0 = Wa[(size_t)k * N + n], v1 = Wa[(size_t)(k + 1) * N + n];
        if (Wb) { v0 -= Wb[(size_t)k * N + n]; v1 -= Wb[(size_t)(k + 1) * N + n]; }
        int ch = k >> 5;
        int kpair = (k >> 1) & 15;
        int ksP = kpair >> 3, khi8 = (kpair >> 2) & 1, t4P = kpair & 3;
        int nblk = n >> 7, r = n & 127;
        int ni = r & 31, wn = r >> 5, nf = ni >> 3, gB = ni & 7;
        int slot = ((((wn << 1) + ksP) << 2) + nf) * 64 + (gB << 3) + (t4P << 1) + khi8;
        out[((size_t)nblk * (K >> 5) + ch) * 2048 + slot] = h2u(__floats2half2_rn(v0, v1));
    }
}

// ---------------- fp16 mma GEMM ----------------
// MODE 0: plain half A. MODE 1: relu(affine(A)). MODE 2: relu(affine(P[sdst]+Q[ssrc]+comb))
// STATS: unweighted per-channel sum/sumsq of outputs (edge GEMMs).
// NSTAT: blockIdx.y selects (Bp,Co) vs (Bp2,Co2); epilogue accumulates din/dout-weighted stats.
template <int MODE, bool STATS, bool NSTAT, int NB>
__global__ void __launch_bounds__(256, 2)
wm_gemm(const __half* __restrict__ A, const __half* __restrict__ Qb,
        const uint32_t* __restrict__ Bp, const uint32_t* __restrict__ Bp2,
        const float* __restrict__ bias, const float* __restrict__ comb,
        __half* __restrict__ Co, __half* __restrict__ Co2,
        int M, int K) {
    __shared__ uint32_t sAu[2][1024];
    __shared__ float Ssum[NB * 128], Ssq[NB * 128];
    const int N = NB * 128;
    const int tid = threadIdx.x;
    const int w = tid >> 5, lane = tid & 31;
    const int g = lane >> 2, t4 = lane & 3;
    const int warpM = w & 1, warpN = w >> 1;
    const int m0 = blockIdx.x * 64;
    const int ysel = NSTAT ? blockIdx.y : 0;
    const uint32_t* Bu = (NSTAT && ysel) ? Bp2 : Bp;
    __half* Cu = (NSTAT && ysel) ? Co2 : Co;

    if (STATS || NSTAT) {
#pragma unroll
        for (int i = tid; i < NB * 128; i += 256) { Ssum[i] = 0.f; Ssq[i] = 0.f; }
    }

    float c[NB][2][4][4];
#pragma unroll
    for (int nb = 0; nb < NB; nb++)
#pragma unroll
        for (int i = 0; i < 2; i++)
#pragma unroll
            for (int j = 0; j < 4; j++)
#pragma unroll
                for (int k = 0; k < 4; k++) c[nb][i][j][k] = 0.f;

    const int rowlane = lane >> 2, kq8 = lane & 3;
    const int r = (w << 3) + rowlane;
    const int gm = m0 + r;
    const bool valid = gm < M;
    int rd = 0, rs = 0;
    if (MODE == 2) { rd = valid ? g_sdst[gm] : 0; rs = valid ? g_ssrc[gm] : 0; }
    int slotk[4];
    {
        const int wm = r >> 5, ri = r & 31, mf = ri >> 4, rb = ri & 15;
        const int gA = rb & 7, rowhi = rb >> 3;
        const int ksP = kq8 >> 1, khi8 = kq8 & 1;
#pragma unroll
        for (int i = 0; i < 4; i++)
            slotk[i] = ((((wm << 1) + ksP) << 1) + mf) * 128 + (gA << 4) + (i << 2) + rowhi + (khi8 << 1);
    }
    const int nch = K >> 5;

    auto load_regs = [&](int ch, uint32_t* hu) {
        const int cg = (ch << 5) + (kq8 << 3);
        if (!valid) { hu[0] = hu[1] = hu[2] = hu[3] = 0; return; }
        if (MODE == 0) {
            uint4 v = *(const uint4*)(A + (size_t)gm * K + cg);
            hu[0] = v.x; hu[1] = v.y; hu[2] = v.z; hu[3] = v.w;
            return;
        }
        float4 al0 = *(const float4*)(g_alpha + cg);
        float4 al1 = *(const float4*)(g_alpha + cg + 4);
        float4 be0 = *(const float4*)(g_beta + cg);
        float4 be1 = *(const float4*)(g_beta + cg + 4);
        if (MODE == 2) {
            float4 cb0 = *(const float4*)(comb + cg);
            float4 cb1 = *(const float4*)(comb + cg + 4);
            be0.x = fmaf(al0.x, cb0.x, be0.x); be0.y = fmaf(al0.y, cb0.y, be0.y);
            be0.z = fmaf(al0.z, cb0.z, be0.z); be0.w = fmaf(al0.w, cb0.w, be0.w);
            be1.x = fmaf(al1.x, cb1.x, be1.x); be1.y = fmaf(al1.y, cb1.y, be1.y);
            be1.z = fmaf(al1.z, cb1.z, be1.z); be1.w = fmaf(al1.w, cb1.w, be1.w);
        }
        if (MODE == 1) {
            uint4 v = *(const uint4*)(A + (size_t)gm * K + cg);
            hu[0] = aff2(v.x, al0.x, al0.y, be0.x, be0.y);
            hu[1] = aff2(v.y, al0.z, al0.w, be0.z, be0.w);
            hu[2] = aff2(v.z, al1.x, al1.y, be1.x, be1.y);
            hu[3] = aff2(v.w, al1.z, al1.w, be1.z, be1.w);
        } else {
            uint4 pv = *(const uint4*)(A + (size_t)rd * K + cg);
            uint4 qv = *(const uint4*)(Qb + (size_t)rs * K + cg);
            hu[0] = aff2s(pv.x, qv.x, al0.x, al0.y, be0.x, be0.y);
            hu[1] = aff2s(pv.y, qv.y, al0.z, al0.w, be0.z, be0.w);
            hu[2] = aff2s(pv.z, qv.z, al1.x, al1.y, be1.x, be1.y);
            hu[3] = aff2s(pv.w, qv.w, al1.z, al1.w, be1.z, be1.w);
        }
    };

    uint32_t hu[4];
    load_regs(0, hu);
#pragma unroll
    for (int j = 0; j < 4; j++) sAu[0][slotk[j]] = hu[j];
    __syncthreads();

    for (int ch = 0; ch < nch; ch++) {
        uint32_t hn[4];
        if (ch + 1 < nch) load_regs(ch + 1, hn);

        const uint4* A4 = (const uint4*)sAu[ch & 1];
#pragma unroll
        for (int ks = 0; ks < 2; ks++) {
            uint4 af[2];
#pragma unroll
            for (int mf = 0; mf < 2; mf++)
                af[mf] = A4[((((warpM << 1) + ks) << 1) + mf) * 32 + lane];
#pragma unroll
            for (int nb = 0; nb < NB; nb++) {
                const uint2* B2 = (const uint2*)(Bu + ((size_t)nb * nch + ch) * 2048);
                uint2 bf[4];
#pragma unroll
                for (int nf = 0; nf < 4; nf++)
                    bf[nf] = B2[((((warpN << 1) + ks) << 2) + nf) * 32 + lane];
#pragma unroll
                for (int mf = 0; mf < 2; mf++)
#pragma unroll
                    for (int nf = 0; nf < 4; nf++) {
                        asm volatile(
                            "mma.sync.aligned.m16n8k16.row.col.f32.f16.f16.f32 "
                            "{%0,%1,%2,%3}, {%4,%5,%6,%7}, {%8,%9}, {%0,%1,%2,%3};"
                            : "+f"(c[nb][mf][nf][0]), "+f"(c[nb][mf][nf][1]),
                              "+f"(c[nb][mf][nf][2]), "+f"(c[nb][mf][nf][3])
                            : "r"(af[mf].x), "r"(af[mf].y), "r"(af[mf].z), "r"(af[mf].w),
                              "r"(bf[nf].x), "r"(bf[nf].y));
                    }
            }
        }
        if (ch + 1 < nch) {
#pragma unroll
            for (int j = 0; j < 4; j++) sAu[(ch + 1) & 1][slotk[j]] = hn[j];
        }
        __syncthreads();
    }

#pragma unroll
    for (int mf = 0; mf < 2; mf++) {
        int r0 = m0 + warpM * 32 + mf * 16 + g;
        float w0 = 0.f, w8 = 0.f;
        if (NSTAT) {
            if (r0 < M)     w0 = ysel ? (float)g_dout[r0]     : (float)(g_seg[r0 + 1] - g_seg[r0]);
            if (r0 + 8 < M) w8 = ysel ? (float)g_dout[r0 + 8] : (float)(g_seg[r0 + 9] - g_seg[r0 + 8]);
        }
#pragma unroll
        for (int nb = 0; nb < NB; nb++)
#pragma unroll
            for (int nf = 0; nf < 4; nf++) {
                int colL = nb * 128 + warpN * 32 + nf * 8 + 2 * t4;
                float b0 = bias ? bias[colL] : 0.f;
                float b1 = bias ? bias[colL + 1] : 0.f;
                float v0 = c[nb][mf][nf][0] + b0, v1 = c[nb][mf][nf][1] + b1;
                float v2 = c[nb][mf][nf][2] + b0, v3 = c[nb][mf][nf][3] + b1;
                if (r0 < M)
                    *(__half2*)(Cu + (size_t)r0 * N + colL) = __floats2half2_rn(v0, v1);
                if (r0 + 8 < M)
                    *(__half2*)(Cu + (size_t)(r0 + 8) * N + colL) = __floats2half2_rn(v2, v3);
                if (STATS) {
                    atomicAdd(&Ssum[colL], v0 + v2);
                    atomicAdd(&Ssum[colL + 1], v1 + v3);
                    atomicAdd(&Ssq[colL], fmaf(v0, v0, v2 * v2));
                    atomicAdd(&Ssq[colL + 1], fmaf(v1, v1, v3 * v3));
                } else if (NSTAT) {
                    // stats on half-rounded values (what edges will consume)
                    float h0 = __half2float(__float2half_rn(v0));
                    float h1 = __half2float(__float2half_rn(v1));
                    float h2v = __half2float(__float2half_rn(v2));
                    float h3v = __half2float(__float2half_rn(v3));
                    atomicAdd(&Ssum[colL], w0 * h0 + w8 * h2v);
                    atomicAdd(&Ssum[colL + 1], w0 * h1 + w8 * h3v);
                    atomicAdd(&Ssq[colL], w0 * h0 * h0 + w8 * h2v * h2v);
                    atomicAdd(&Ssq[colL + 1], w0 * h1 * h1 + w8 * h3v * h3v);
                }
            }
    }
    if (STATS || NSTAT) {
        __syncthreads();
#pragma unroll
        for (int i = tid; i < NB * 128; i += 256) {
            atomicAdd(&g_sum[i], (double)Ssum[i]);
            atomicAdd(&g_sumsq[i], (double)Ssq[i]);
        }
    }
}

// ---------------- segment-reduce aggregations (8 ch/thread) ----------------
__global__ void k_agg_seg(const __half* __restrict__ H, __half* __restrict__ node, int logC) {
    const int sh = logC - 3;
    size_t tot = (size_t)NN << sh;
    for (size_t idx = (size_t)blockIdx.x * blockDim.x + threadIdx.x; idx < tot;
         idx += (size_t)gridDim.x * blockDim.x) {
        int n = (int)(idx >> sh);
        int cc = ((int)idx & ((1 << sh) - 1)) << 3;
        float4 al0 = *(const float4*)(g_alpha + cc);
        float4 al1 = *(const float4*)(g_alpha + cc + 4);
        float4 be0 = *(const float4*)(g_beta + cc);
        float4 be1 = *(const float4*)(g_beta + cc + 4);
        int p0 = g_seg[n], p1 = g_seg[n + 1];
        float s[8];
#pragma unroll
        for (int i = 0; i < 8; i++) s[i] = 0.f;
        for (int p = p0; p < p1; p++) {
            uint4 hv = *(const uint4*)(H + ((size_t)p << logC) + cc);
            float2 a;
            a = uf2(hv.x);
            s[0] += fmaxf(fmaf(al0.x, a.x, be0.x), 0.f);
            s[1] += fmaxf(fmaf(al0.y, a.y, be0.y), 0.f);
            a = uf2(hv.y);
            s[2] += fmaxf(fmaf(al0.z, a.x, be0.z), 0.f);
            s[3] += fmaxf(fmaf(al0.w, a.y, be0.w), 0.f);
            a = uf2(hv.z);
            s[4] += fmaxf(fmaf(al1.x, a.x, be1.x), 0.f);
            s[5] += fmaxf(fmaf(al1.y, a.y, be1.y), 0.f);
            a = uf2(hv.w);
            s[6] += fmaxf(fmaf(al1.z, a.x, be1.z), 0.f);
            s[7] += fmaxf(fmaf(al1.w, a.y, be1.w), 0.f);
        }
        float inv = g_invdeg[n];
        uint4 o;
        o.x = h2u(__floats2half2_rn(s[0] * inv, s[1] * inv));
        o.y = h2u(__floats2half2_rn(s[2] * inv, s[3] * inv));
        o.z = h2u(__floats2half2_rn(s[4] * inv, s[5] * inv));
        o.w = h2u(__floats2half2_rn(s[6] * inv, s[7] * inv));
        *(uint4*)(node + ((size_t)n << logC) + cc) = o;
    }
}

__global__ void k_agg_pq_seg(const __half* __restrict__ P, const __half* __restrict__ Qb,
                             const float* __restrict__ comb, __half* __restrict__ node) {
    size_t tot = (size_t)NN * 32;
    for (size_t idx = (size_t)blockIdx.x * blockDim.x + threadIdx.x; idx < tot;
         idx += (size_t)gridDim.x * blockDim.x) {
        int n = (int)(idx >> 5);
        int cc = ((int)idx & 31) << 3;
        float4 al0 = *(const float4*)(g_alpha + cc);
        float4 al1 = *(const float4*)(g_alpha + cc + 4);
        float4 be0 = *(const float4*)(g_beta + cc);
        float4 be1 = *(const float4*)(g_beta + cc + 4);
        float4 cb0 = *(const float4*)(comb + cc);
        float4 cb1 = *(const float4*)(comb + cc + 4);
        uint4 pv = *(const uint4*)(P + ((size_t)n << 8) + cc);
        float pb[8];
        {
            float2 a;
            a = uf2(pv.x); pb[0] = a.x + cb0.x; pb[1] = a.y + cb0.y;
            a = uf2(pv.y); pb[2] = a.x + cb0.z; pb[3] = a.y + cb0.w;
            a = uf2(pv.z); pb[4] = a.x + cb1.x; pb[5] = a.y + cb1.y;
            a = uf2(pv.w); pb[6] = a.x + cb1.z; pb[7] = a.y + cb1.w;
        }
        int p0 = g_seg[n], p1 = g_seg[n + 1];
        float s[8];
#pragma unroll
        for (int i = 0; i < 8; i++) s[i] = 0.f;
        for (int p = p0; p < p1; p++) {
            int sidx = g_ssrc[p];
            uint4 qv = *(const uint4*)(Qb + ((size_t)sidx << 8) + cc);
            float2 a;
            a = uf2(qv.x);
            s[0] += fmaxf(fmaf(al0.x, pb[0] + a.x, be0.x), 0.f);
            s[1] += fmaxf(fmaf(al0.y, pb[1] + a.y, be0.y), 0.f);
            a = uf2(qv.y);
            s[2] += fmaxf(fmaf(al0.z, pb[2] + a.x, be0.z), 0.f);
            s[3] += fmaxf(fmaf(al0.w, pb[3] + a.y, be0.w), 0.f);
            a = uf2(qv.z);
            s[4] += fmaxf(fmaf(al1.x, pb[4] + a.x, be1.x), 0.f);
            s[5] += fmaxf(fmaf(al1.y, pb[5] + a.y, be1.y), 0.f);
            a = uf2(qv.w);
            s[6] += fmaxf(fmaf(al1.z, pb[6] + a.x, be1.z), 0.f);
            s[7] += fmaxf(fmaf(al1.w, pb[7] + a.y, be1.w), 0.f);
        }
        float inv = g_invdeg[n];
        uint4 o;
        o.x = h2u(__floats2half2_rn(s[0] * inv, s[1] * inv));
        o.y = h2u(__floats2half2_rn(s[2] * inv, s[3] * inv));
        o.z = h2u(__floats2half2_rn(s[4] * inv, s[5] * inv));
        o.w = h2u(__floats2half2_rn(s[6] * inv, s[7] * inv));
        *(uint4*)(node + ((size_t)n << 8) + cc) = o;
    }
}

__global__ void k_pool_seg(const __half* __restrict__ h3) {
    int gph = blockIdx.x, t = threadIdx.x;
    int n0 = g_gseg[gph], n1 = g_gseg[gph + 1];
    float s = 0.f;
    for (int n = n0; n < n1; n++) s += __half2float(h3[(size_t)n * 256 + t]);
    g_pool[gph * 256 + t] = s / fmaxf((float)(n1 - n0), 1.f);
}

__global__ void k_head(const float* __restrict__ W1, const float* __restrict__ b1,
                       const float* __restrict__ W2, const float* __restrict__ b2,
                       float* __restrict__ out) {
    __shared__ float gv[256], hid[256], r0[256], r1[256];
    int r = blockIdx.x, t = threadIdx.x;
    gv[t] = g_pool[r * 256 + t];
    __syncthreads();
    float a = b1[t];
    for (int k = 0; k < 256; k++) a = fmaf(gv[k], W1[k * 256 + t], a);
    hid[t] = fmaxf(a, 0.f);
    __syncthreads();
    r0[t] = hid[t] * W2[t * 2 + 0];
    r1[t] = hid[t] * W2[t * 2 + 1];
    __syncthreads();
    for (int s = 128; s > 0; s >>= 1) {
        if (t < s) { r0[t] += r0[t + s]; r1[t] += r1[t + s]; }
        __syncthreads();
    }
    if (t == 0) {
        out[r * 2 + 0] = r0[0] + b2[0];
        out[r * 2 + 1] = r1[0] + b2[1];
    }
}

// ---------------- launcher ----------------
extern "C" void kernel_launch(void* const* d_in, const int* in_sizes, int n_in,
                              void* d_out, int out_size) {
    const float* x      = (const float*)d_in[0];
    const void*  ei     = d_in[1];
    const void*  bt     = d_in[2];
    const float* c1_w1  = (const float*)d_in[3];
    const float* c1_b1  = (const float*)d_in[4];
    const float* c1_gn1 = (const float*)d_in[5];
    const float* c1_w2  = (const float*)d_in[6];
    const float* c1_b2  = (const float*)d_in[7];
    const float* c1_gn2 = (const float*)d_in[8];
    const float* c1_w3  = (const float*)d_in[9];
    const float* c1_b3  = (const float*)d_in[10];
    const float* c1_gn3 = (const float*)d_in[11];
    const float* c2_w1  = (const float*)d_in[12];
    const float* c2_b1  = (const float*)d_in[13];
    const float* c2_gn1 = (const float*)d_in[14];
    const float* c2_w2  = (const float*)d_in[15];
    const float* c2_b2  = (const float*)d_in[16];
    const float* c2_gn2 = (const float*)d_in[17];
    const float* c3_w1  = (const float*)d_in[18];
    const float* c3_b1  = (const float*)d_in[19];
    const float* c3_gn1 = (const float*)d_in[20];
    const float* lw1    = (const float*)d_in[21];
    const float* lb1    = (const float*)d_in[22];
    const float* lw2    = (const float*)d_in[23];
    const float* lb2    = (const float*)d_in[24];
    float* out = (float*)d_out;
    (void)in_sizes; (void)n_in; (void)out_size;

    __half *pP, *pQ, *ph1, *ph2, *ph3, *pe0, *pe1;
    uint32_t *pwt, *pwtA, *pwtB;
    int *phist, *pdout, *pghist;
    cudaGetSymbolAddress((void**)&pP, g_P);
    cudaGetSymbolAddress((void**)&pQ, g_Q);
    cudaGetSymbolAddress((void**)&ph1, g_h1);
    cudaGetSymbolAddress((void**)&ph2, g_h2);
    cudaGetSymbolAddress((void**)&ph3, g_h3);
    cudaGetSymbolAddress((void**)&pe0, g_e0);
    cudaGetSymbolAddress((void**)&pe1, g_e1);
    cudaGetSymbolAddress((void**)&pwt, g_wtp);
    cudaGetSymbolAddress((void**)&pwtA, g_wtpA);
    cudaGetSymbolAddress((void**)&pwtB, g_wtpB);
    cudaGetSymbolAddress((void**)&phist, g_hist);
    cudaGetSymbolAddress((void**)&pdout, g_dout);
    cudaGetSymbolAddress((void**)&pghist, g_ghist);

    // setup
    cudaMemsetAsync(phist, 0, NN * sizeof(int));
    cudaMemsetAsync(pdout, 0, NN * sizeof(int));
    cudaMemsetAsync(pghist, 0, NG * sizeof(int));
    k_convert<<<1024, 256>>>(ei, bt);
    k_scan_nodes<<<1, 1024>>>();
    k_scan_graphs<<<1, 1024>>>();
    k_scatter<<<1024, 256>>>();

    const int ET = NE / 64;
    const int NT = (NN + 63) / 64;

    // block 1 (C=128, 3 layers); k_l1 fuses node-term stats
    k_l1<<<512, 128>>>(x, c1_w1);
    k_cross<<<2048, 256>>>(pP, pQ, 7);
    k_finalize<<<1, 256>>>(c1_gn1, 128, c1_b1);
    k_trp<<<64, 256>>>(c1_w2, nullptr, pwt, 128, 128);
    wm_gemm<2, true, false, 1><<<ET, 256>>>(pP, pQ, pwt, nullptr, c1_b2, c1_b1, pe0, nullptr, NE, 128);
    k_finalize<<<1, 256>>>(c1_gn2, 128, nullptr);
    k_trp<<<64, 256>>>(c1_w3, nullptr, pwtA, 128, 128);
    wm_gemm<1, true, false, 1><<<ET, 256>>>(pe0, nullptr, pwtA, nullptr, c1_b3, nullptr, pe1, nullptr, NE, 128);
    k_finalize<<<1, 256>>>(c1_gn3, 128, nullptr);
    k_agg_seg<<<4096, 256>>>(pe1, ph1, 7);

    // block 2 (C=256, 2 layers); merged node GEMM pair with fused node stats
    k_trp<<<128, 256>>>(c2_w1, c2_w1 + 128 * 256, pwtA, 128, 256);
    k_trp<<<128, 256>>>(c2_w1 + 128 * 256, nullptr, pwtB, 128, 256);
    wm_gemm<0, false, true, 2><<<dim3(NT, 2), 256>>>(ph1, nullptr, pwtA, pwtB, nullptr, nullptr, pP, pQ, NN, 128);
    k_cross<<<2048, 256>>>(pP, pQ, 8);
    k_finalize<<<1, 256>>>(c2_gn1, 256, c2_b1);
    k_trp<<<256, 256>>>(c2_w2, nullptr, pwt, 256, 256);
    wm_gemm<2, true, false, 2><<<ET, 256>>>(pP, pQ, pwt, nullptr, c2_b2, c2_b1, pe0, nullptr, NE, 256);
    k_finalize<<<1, 256>>>(c2_gn2, 256, nullptr);
    k_agg_seg<<<8192, 256>>>(pe0, ph2, 8);

    // block 3 (C=256, 1 layer — no edge GEMM)
    k_trp<<<256, 256>>>(c3_w1, c3_w1 + 256 * 256, pwtA, 256, 256);
    k_trp<<<256, 256>>>(c3_w1 + 256 * 256, nullptr, pwtB, 256, 256);
    wm_gemm<0, false, true, 2><<<dim3(NT, 2), 256>>>(ph2, nullptr, pwtA, pwtB, nullptr, nullptr, pP, pQ, NN, 256);
    k_cross<<<2048, 256>>>(pP, pQ, 8);
    k_finalize<<<1, 256>>>(c3_gn1, 256, c3_b1);
    k_agg_pq_seg<<<4096, 256>>>(pP, pQ, c3_b1, ph3);

    // pool + head
    k_pool_seg<<<NG, 256>>>(ph3);
    k_head<<<NG, 256>>>(lw1, lb1, lw2, lb2, out);
}

// round 13
// speedup vs baseline: 1.2730x; 1.2730x over previous
#include <cuda_runtime.h>
#include <cuda_fp16.h>
#include <cstdint>

#define NN 100000
#define NE 400000
#define NG 1000
#define EPSV 1e-5f

__device__ __half g_P[(size_t)NN * 256];
__device__ __half g_Q[(size_t)NN * 256];
__device__ __half g_h1[(size_t)NN * 128];
__device__ __half g_h2[(size_t)NN * 256];
__device__ __half g_h3[(size_t)NN * 256];
__device__ __half g_e0[(size_t)NE * 256];
__device__ __half g_e1[(size_t)NE * 128];
__device__ int    g_src[NE];
__device__ int    g_dst[NE];
__device__ int    g_ssrc[NE];
__device__ int    g_sdst[NE];
__device__ int    g_batch[NN];
__device__ int    g_hist[NN];
__device__ int    g_dout[NN];
__device__ int    g_seg[NN + 1];
__device__ int    g_cur[NN];
__device__ int    g_ghist[NG];
__device__ int    g_gseg[NG + 1];
__device__ float  g_invdeg[NN];
__device__ double g_sum[256];
__device__ double g_sumsq[256];
__device__ float  g_alpha[256];
__device__ float  g_beta[256];
__device__ uint32_t g_wtp [2 * 8 * 2048];
__device__ uint32_t g_wtpA[2 * 8 * 2048];
__device__ uint32_t g_wtpB[2 * 8 * 2048];
__device__ float  g_pool[NG * 256];

__device__ __forceinline__ uint32_t h2u(__half2 h) { return *reinterpret_cast<uint32_t*>(&h); }
__device__ __forceinline__ __half2 u2h(uint32_t u) { return *reinterpret_cast<__half2*>(&u); }
__device__ __forceinline__ float2 uf2(uint32_t u) { return __half22float2(u2h(u)); }

__device__ __forceinline__ uint32_t aff2(uint32_t u, float ax, float ay, float bx, float by) {
    float2 f = uf2(u);
    return h2u(__floats2half2_rn(fmaxf(fmaf(ax, f.x, bx), 0.f),
                                 fmaxf(fmaf(ay, f.y, by), 0.f)));
}
__device__ __forceinline__ uint32_t aff2s(uint32_t up, uint32_t uq,
                                          float ax, float ay, float bx, float by) {
    float2 p = uf2(up), q = uf2(uq);
    return h2u(__floats2half2_rn(fmaxf(fmaf(ax, p.x + q.x, bx), 0.f),
                                 fmaxf(fmaf(ay, p.y + q.y, by), 0.f)));
}

// ---------------- convert + histograms ----------------
__global__ void k_convert(const void* __restrict__ ei, const void* __restrict__ bt) {
    __shared__ int s64;
    if (threadIdx.x == 0) {
        const unsigned long long* e = (const unsigned long long*)ei;
        int f = 1;
        for (int i = 0; i < 256; i++)
            if (e[i] >= (unsigned long long)NN) { f = 0; break; }
        s64 = f;
    }
    __syncthreads();
    const int is64 = s64;
    int i0 = blockIdx.x * blockDim.x + threadIdx.x;
    int st = gridDim.x * blockDim.x;
    for (int k = i0; k < NE; k += st) {
        int s, d;
        if (is64) {
            const long long* e = (const long long*)ei;
            s = (int)e[k]; d = (int)e[NE + k];
        } else {
            const int* e = (const int*)ei;
            s = e[k]; d = e[NE + k];
        }
        g_src[k] = s; g_dst[k] = d;
        atomicAdd(&g_hist[d], 1);
        atomicAdd(&g_dout[s], 1);
    }
    for (int k = i0; k < NN; k += st) {
        int b = is64 ? (int)((const long long*)bt)[k] : ((const int*)bt)[k];
        g_batch[k] = b;
        atomicAdd(&g_ghist[b], 1);
    }
}

__global__ void k_scan_nodes() {
    __shared__ int wsum[32];
    __shared__ int carry;
    int t = threadIdx.x, lane = t & 31, wid = t >> 5;
    if (t == 0) carry = 0;
    __syncthreads();
    for (int base = 0; base < NN; base += 1024) {
        int i = base + t;
        int v = (i < NN) ? g_hist[i] : 0;
        int x = v;
#pragma unroll
        for (int off = 1; off < 32; off <<= 1) {
            int y = __shfl_up_sync(0xFFFFFFFFu, x, off);
            if (lane >= off) x += y;
        }
        if (lane == 31) wsum[wid] = x;
        __syncthreads();
        if (wid == 0) {
            int wv = wsum[lane];
#pragma unroll
            for (int off = 1; off < 32; off <<= 1) {
                int y = __shfl_up_sync(0xFFFFFFFFu, wv, off);
                if (lane >= off) wv += y;
            }
            wsum[lane] = wv;
        }
        __syncthreads();
        int incl = x + (wid ? wsum[wid - 1] : 0);
        int c = carry;
        if (i < NN) {
            g_seg[i] = c + incl - v;
            g_cur[i] = c + incl - v;
            g_invdeg[i] = 1.f / fmaxf((float)v, 1.f);
        }
        __syncthreads();
        if (t == 1023) carry += incl;
        __syncthreads();
    }
    if (t == 0) g_seg[NN] = carry;
}

__global__ void k_scan_graphs() {
    __shared__ int sb[1024];
    int t = threadIdx.x;
    int v = (t < NG) ? g_ghist[t] : 0;
    sb[t] = v;
    __syncthreads();
    for (int off = 1; off < 1024; off <<= 1) {
        int x = sb[t];
        int y = (t >= off) ? sb[t - off] : 0;
        __syncthreads();
        sb[t] = x + y;
        __syncthreads();
    }
    if (t < NG) g_gseg[t] = sb[t] - v;
    if (t == 1023) g_gseg[NG] = sb[1023];
}

__global__ void k_scatter() {
    int i = blockIdx.x * blockDim.x + threadIdx.x;
    for (; i < NE; i += gridDim.x * blockDim.x) {
        int d = g_dst[i];
        int p = atomicAdd(&g_cur[d], 1);
        g_ssrc[p] = g_src[i];
        g_sdst[p] = d;
    }
}

// layer-1 of block 1
__global__ void k_l1(const float* __restrict__ x, const float* __restrict__ W) {
    __shared__ float wd[5 * 128], wb[5 * 128];
    int c = threadIdx.x;
#pragma unroll
    for (int k = 0; k < 5; k++) {
        float t = W[(5 + k) * 128 + c];
        wb[k * 128 + c] = t;
        wd[k * 128 + c] = W[k * 128 + c] - t;
    }
    __syncthreads();
    for (int n = blockIdx.x; n < NN; n += gridDim.x) {
        float xv[5];
#pragma unroll
        for (int k = 0; k < 5; k++) xv[k] = x[n * 5 + k];
        float p = 0.f, q = 0.f;
#pragma unroll
        for (int k = 0; k < 5; k++) {
            p = fmaf(xv[k], wd[k * 128 + c], p);
            q = fmaf(xv[k], wb[k * 128 + c], q);
        }
        g_P[(size_t)n * 128 + c] = __float2half_rn(p);
        g_Q[(size_t)n * 128 + c] = __float2half_rn(q);
    }
}

// ---- factorized edge stats, 8 channels/thread (uint4 gathers) ----
__global__ void k_stats2(const __half* __restrict__ P, const __half* __restrict__ Qb, int logC) {
    __shared__ float Ss[256], Sq[256];
    const int opn = 1 << (logC - 3);   // octs per node
    const int t = threadIdx.x;
    const int nlane = t >> (logC - 3);
    const int npb = 256 >> (logC - 3);
    const int cc = (t & (opn - 1)) << 3;
    if (t < (1 << logC)) { Ss[t] = 0.f; Sq[t] = 0.f; }

    float s[8], q[8];
#pragma unroll
    for (int i = 0; i < 8; i++) { s[i] = 0.f; q[i] = 0.f; }

    const int ngroups = (NN + npb - 1) / npb;
    for (int ng = blockIdx.x; ng < ngroups; ng += gridDim.x) {
        int n = ng * npb + nlane;
        if (n >= NN) continue;
        int p0 = g_seg[n], p1 = g_seg[n + 1];
        float din = (float)(p1 - p0);
        float dout = (float)g_dout[n];
        uint4 pv = *(const uint4*)(P + ((size_t)n << logC) + cc);
        uint4 qv = *(const uint4*)(Qb + ((size_t)n << logC) + cc);
        float pf[8], qf[8];
        {
            float2 a;
            a = uf2(pv.x); pf[0] = a.x; pf[1] = a.y;
            a = uf2(pv.y); pf[2] = a.x; pf[3] = a.y;
            a = uf2(pv.z); pf[4] = a.x; pf[5] = a.y;
            a = uf2(pv.w); pf[6] = a.x; pf[7] = a.y;
            a = uf2(qv.x); qf[0] = a.x; qf[1] = a.y;
            a = uf2(qv.y); qf[2] = a.x; qf[3] = a.y;
            a = uf2(qv.z); qf[4] = a.x; qf[5] = a.y;
            a = uf2(qv.w); qf[6] = a.x; qf[7] = a.y;
        }
        float r[8];
#pragma unroll
        for (int i = 0; i < 8; i++) r[i] = 0.f;
        for (int p = p0; p < p1; p++) {
            int sidx = g_ssrc[p];
            uint4 sv = *(const uint4*)(Qb + ((size_t)sidx << logC) + cc);
            float2 a;
            a = uf2(sv.x); r[0] += a.x; r[1] += a.y;
            a = uf2(sv.y); r[2] += a.x; r[3] += a.y;
            a = uf2(sv.z); r[4] += a.x; r[5] += a.y;
            a = uf2(sv.w); r[6] += a.x; r[7] += a.y;
        }
#pragma unroll
        for (int i = 0; i < 8; i++) {
            s[i] += din * pf[i] + dout * qf[i];
            q[i] += din * pf[i] * pf[i] + dout * qf[i] * qf[i] + 2.f * pf[i] * r[i];
        }
    }
    __syncthreads();
#pragma unroll
    for (int i = 0; i < 8; i++) {
        atomicAdd(&Ss[cc + i], s[i]);
        atomicAdd(&Sq[cc + i], q[i]);
    }
    __syncthreads();
    if (t < (1 << logC)) {
        atomicAdd(&g_sum[t], (double)Ss[t]);
        atomicAdd(&g_sumsq[t], (double)Sq[t]);
    }
}

__global__ void k_finalize(const float* __restrict__ gn, int C, const float* __restrict__ comb) {
    int c = threadIdx.x;
    if (c < C) {
        double s = g_sum[c], q = g_sumsq[c];
        if (comb) {
            double bc = (double)comb[c];
            q += 2.0 * bc * s + (double)NE * bc * bc;
            s += (double)NE * bc;
        }
        float invE = 1.f / (float)NE;
        float m  = (float)(s * invE);
        float m2 = (float)(q * invE);
        float g = gn[c], b = gn[C + c], ms = gn[2 * C + c];
        float var = m2 - 2.f * ms * m * m + ms * ms * m * m;
        float rs = rsqrtf(var + EPSV);
        g_alpha[c] = g * rs;
        g_beta[c]  = b - g * rs * ms * m;
        g_sum[c] = 0.0;
        g_sumsq[c] = 0.0;
    }
}

// pre-permute weights into mma B-fragment layout
__global__ void k_trp(const float* __restrict__ Wa, const float* __restrict__ Wb,
                      uint32_t* __restrict__ out, int K, int N) {
    int tot = N * (K >> 1);
    int i = blockIdx.x * blockDim.x + threadIdx.x;
    for (; i < tot; i += gridDim.x * blockDim.x) {
        int n = i / (K >> 1);
        int kp = i - n * (K >> 1);
        int k = kp << 1;
        float v0 = Wa[(size_t)k * N + n], v1 = Wa[(size_t)(k + 1) * N + n];
        if (Wb) { v0 -= Wb[(size_t)k * N + n]; v1 -= Wb[(size_t)(k + 1) * N + n]; }
        int ch = k >> 5;
        int kpair = (k >> 1) & 15;
        int ksP = kpair >> 3, khi8 = (kpair >> 2) & 1, t4P = kpair & 3;
        int nblk = n >> 7, r = n & 127;
        int ni = r & 31, wn = r >> 5, nf = ni >> 3, gB = ni & 7;
        int slot = ((((wn << 1) + ksP) << 2) + nf) * 64 + (gB << 3) + (t4P << 1) + khi8;
        out[((size_t)nblk * (K >> 5) + ch) * 2048 + slot] = h2u(__floats2half2_rn(v0, v1));
    }
}

// ---------------- fp16 mma GEMM ----------------
// MODE 0: plain half A. MODE 1: relu(affine(A)). MODE 2: relu(affine(P[sdst]+Q[ssrc]+comb))
// STATS: unweighted per-channel sum/sumsq of outputs (edge GEMMs).
// PAIR: blockIdx.y selects (Bp,Co) vs (Bp2,Co2) — merged P/Q node GEMM pair.
template <int MODE, bool STATS, bool PAIR, int NB>
__global__ void __launch_bounds__(256, 2)
wm_gemm(const __half* __restrict__ A, const __half* __restrict__ Qb,
        const uint32_t* __restrict__ Bp, const uint32_t* __restrict__ Bp2,
        const float* __restrict__ bias, const float* __restrict__ comb,
        __half* __restrict__ Co, __half* __restrict__ Co2,
        int M, int K) {
    __shared__ uint32_t sAu[2][1024];
    __shared__ float Ssum[NB * 128], Ssq[NB * 128];
    const int N = NB * 128;
    const int tid = threadIdx.x;
    const int w = tid >> 5, lane = tid & 31;
    const int g = lane >> 2, t4 = lane & 3;
    const int warpM = w & 1, warpN = w >> 1;
    const int m0 = blockIdx.x * 64;
    const uint32_t* Bu = (PAIR && blockIdx.y) ? Bp2 : Bp;
    __half* Cu = (PAIR && blockIdx.y) ? Co2 : Co;

    if (STATS) {
#pragma unroll
        for (int i = tid; i < NB * 128; i += 256) { Ssum[i] = 0.f; Ssq[i] = 0.f; }
    }

    float c[NB][2][4][4];
#pragma unroll
    for (int nb = 0; nb < NB; nb++)
#pragma unroll
        for (int i = 0; i < 2; i++)
#pragma unroll
            for (int j = 0; j < 4; j++)
#pragma unroll
                for (int k = 0; k < 4; k++) c[nb][i][j][k] = 0.f;

    const int rowlane = lane >> 2, kq8 = lane & 3;
    const int r = (w << 3) + rowlane;
    const int gm = m0 + r;
    const bool valid = gm < M;
    int rd = 0, rs = 0;
    if (MODE == 2) { rd = valid ? g_sdst[gm] : 0; rs = valid ? g_ssrc[gm] : 0; }
    int slotk[4];
    {
        const int wm = r >> 5, ri = r & 31, mf = ri >> 4, rb = ri & 15;
        const int gA = rb & 7, rowhi = rb >> 3;
        const int ksP = kq8 >> 1, khi8 = kq8 & 1;
#pragma unroll
        for (int i = 0; i < 4; i++)
            slotk[i] = ((((wm << 1) + ksP) << 1) + mf) * 128 + (gA << 4) + (i << 2) + rowhi + (khi8 << 1);
    }
    const int nch = K >> 5;

    auto load_regs = [&](int ch, uint32_t* hu) {
        const int cg = (ch << 5) + (kq8 << 3);
        if (!valid) { hu[0] = hu[1] = hu[2] = hu[3] = 0; return; }
        if (MODE == 0) {
            uint4 v = *(const uint4*)(A + (size_t)gm * K + cg);
            hu[0] = v.x; hu[1] = v.y; hu[2] = v.z; hu[3] = v.w;
            return;
        }
        float4 al0 = *(const float4*)(g_alpha + cg);
        float4 al1 = *(const float4*)(g_alpha + cg + 4);
        float4 be0 = *(const float4*)(g_beta + cg);
        float4 be1 = *(const float4*)(g_beta + cg + 4);
        if (MODE == 2) {
            float4 cb0 = *(const float4*)(comb + cg);
            float4 cb1 = *(const float4*)(comb + cg + 4);
            be0.x = fmaf(al0.x, cb0.x, be0.x); be0.y = fmaf(al0.y, cb0.y, be0.y);
            be0.z = fmaf(al0.z, cb0.z, be0.z); be0.w = fmaf(al0.w, cb0.w, be0.w);
            be1.x = fmaf(al1.x, cb1.x, be1.x); be1.y = fmaf(al1.y, cb1.y, be1.y);
            be1.z = fmaf(al1.z, cb1.z, be1.z); be1.w = fmaf(al1.w, cb1.w, be1.w);
        }
        if (MODE == 1) {
            uint4 v = *(const uint4*)(A + (size_t)gm * K + cg);
            hu[0] = aff2(v.x, al0.x, al0.y, be0.x, be0.y);
            hu[1] = aff2(v.y, al0.z, al0.w, be0.z, be0.w);
            hu[2] = aff2(v.z, al1.x, al1.y, be1.x, be1.y);
            hu[3] = aff2(v.w, al1.z, al1.w, be1.z, be1.w);
        } else {
            uint4 pv = *(const uint4*)(A + (size_t)rd * K + cg);
            uint4 qv = *(const uint4*)(Qb + (size_t)rs * K + cg);
            hu[0] = aff2s(pv.x, qv.x, al0.x, al0.y, be0.x, be0.y);
            hu[1] = aff2s(pv.y, qv.y, al0.z, al0.w, be0.z, be0.w);
            hu[2] = aff2s(pv.z, qv.z, al1.x, al1.y, be1.x, be1.y);
            hu[3] = aff2s(pv.w, qv.w, al1.z, al1.w, be1.z, be1.w);
        }
    };

    uint32_t hu[4];
    load_regs(0, hu);
#pragma unroll
    for (int j = 0; j < 4; j++) sAu[0][slotk[j]] = hu[j];
    __syncthreads();

    for (int ch = 0; ch < nch; ch++) {
        uint32_t hn[4];
        if (ch + 1 < nch) load_regs(ch + 1, hn);

        const uint4* A4 = (const uint4*)sAu[ch & 1];
#pragma unroll
        for (int ks = 0; ks < 2; ks++) {
            uint4 af[2];
#pragma unroll
            for (int mf = 0; mf < 2; mf++)
                af[mf] = A4[((((warpM << 1) + ks) << 1) + mf) * 32 + lane];
#pragma unroll
            for (int nb = 0; nb < NB; nb++) {
                const uint2* B2 = (const uint2*)(Bu + ((size_t)nb * nch + ch) * 2048);
                uint2 bf[4];
#pragma unroll
                for (int nf = 0; nf < 4; nf++)
                    bf[nf] = B2[((((warpN << 1) + ks) << 2) + nf) * 32 + lane];
#pragma unroll
                for (int mf = 0; mf < 2; mf++)
#pragma unroll
                    for (int nf = 0; nf < 4; nf++) {
                        asm volatile(
                            "mma.sync.aligned.m16n8k16.row.col.f32.f16.f16.f32 "
                            "{%0,%1,%2,%3}, {%4,%5,%6,%7}, {%8,%9}, {%0,%1,%2,%3};"
                            : "+f"(c[nb][mf][nf][0]), "+f"(c[nb][mf][nf][1]),
                              "+f"(c[nb][mf][nf][2]), "+f"(c[nb][mf][nf][3])
                            : "r"(af[mf].x), "r"(af[mf].y), "r"(af[mf].z), "r"(af[mf].w),
                              "r"(bf[nf].x), "r"(bf[nf].y));
                    }
            }
        }
        if (ch + 1 < nch) {
#pragma unroll
            for (int j = 0; j < 4; j++) sAu[(ch + 1) & 1][slotk[j]] = hn[j];
        }
        __syncthreads();
    }

#pragma unroll
    for (int nb = 0; nb < NB; nb++)
#pragma unroll
        for (int mf = 0; mf < 2; mf++) {
            int r0 = m0 + warpM * 32 + mf * 16 + g;
#pragma unroll
            for (int nf = 0; nf < 4; nf++) {
                int colL = nb * 128 + warpN * 32 + nf * 8 + 2 * t4;
                float b0 = bias ? bias[colL] : 0.f;
                float b1 = bias ? bias[colL + 1] : 0.f;
                float v0 = c[nb][mf][nf][0] + b0, v1 = c[nb][mf][nf][1] + b1;
                float v2 = c[nb][mf][nf][2] + b0, v3 = c[nb][mf][nf][3] + b1;
                if (r0 < M)
                    *(__half2*)(Cu + (size_t)r0 * N + colL) = __floats2half2_rn(v0, v1);
                if (r0 + 8 < M)
                    *(__half2*)(Cu + (size_t)(r0 + 8) * N + colL) = __floats2half2_rn(v2, v3);
                if (STATS) {
                    atomicAdd(&Ssum[colL], v0 + v2);
                    atomicAdd(&Ssum[colL + 1], v1 + v3);
                    atomicAdd(&Ssq[colL], fmaf(v0, v0, v2 * v2));
                    atomicAdd(&Ssq[colL + 1], fmaf(v1, v1, v3 * v3));
                }
            }
        }
    if (STATS) {
        __syncthreads();
#pragma unroll
        for (int i = tid; i < NB * 128; i += 256) {
            atomicAdd(&g_sum[i], (double)Ssum[i]);
            atomicAdd(&g_sumsq[i], (double)Ssq[i]);
        }
    }
}

// ---------------- segment-reduce aggregations (8 ch/thread) ----------------
__global__ void k_agg_seg(const __half* __restrict__ H, __half* __restrict__ node, int logC) {
    const int sh = logC - 3;
    size_t tot = (size_t)NN << sh;
    for (size_t idx = (size_t)blockIdx.x * blockDim.x + threadIdx.x; idx < tot;
         idx += (size_t)gridDim.x * blockDim.x) {
        int n = (int)(idx >> sh);
        int cc = ((int)idx & ((1 << sh) - 1)) << 3;
        float4 al0 = *(const float4*)(g_alpha + cc);
        float4 al1 = *(const float4*)(g_alpha + cc + 4);
        float4 be0 = *(const float4*)(g_beta + cc);
        float4 be1 = *(const float4*)(g_beta + cc + 4);
        int p0 = g_seg[n], p1 = g_seg[n + 1];
        float s[8];
#pragma unroll
        for (int i = 0; i < 8; i++) s[i] = 0.f;
        for (int p = p0; p < p1; p++) {
            uint4 hv = *(const uint4*)(H + ((size_t)p << logC) + cc);
            float2 a;
            a = uf2(hv.x);
            s[0] += fmaxf(fmaf(al0.x, a.x, be0.x), 0.f);
            s[1] += fmaxf(fmaf(al0.y, a.y, be0.y), 0.f);
            a = uf2(hv.y);
            s[2] += fmaxf(fmaf(al0.z, a.x, be0.z), 0.f);
            s[3] += fmaxf(fmaf(al0.w, a.y, be0.w), 0.f);
            a = uf2(hv.z);
            s[4] += fmaxf(fmaf(al1.x, a.x, be1.x), 0.f);
            s[5] += fmaxf(fmaf(al1.y, a.y, be1.y), 0.f);
            a = uf2(hv.w);
            s[6] += fmaxf(fmaf(al1.z, a.x, be1.z), 0.f);
            s[7] += fmaxf(fmaf(al1.w, a.y, be1.w), 0.f);
        }
        float inv = g_invdeg[n];
        uint4 o;
        o.x = h2u(__floats2half2_rn(s[0] * inv, s[1] * inv));
        o.y = h2u(__floats2half2_rn(s[2] * inv, s[3] * inv));
        o.z = h2u(__floats2half2_rn(s[4] * inv, s[5] * inv));
        o.w = h2u(__floats2half2_rn(s[6] * inv, s[7] * inv));
        *(uint4*)(node + ((size_t)n << logC) + cc) = o;
    }
}

__global__ void k_agg_pq_seg(const __half* __restrict__ P, const __half* __restrict__ Qb,
                             const float* __restrict__ comb, __half* __restrict__ node) {
    size_t tot = (size_t)NN * 32;
    for (size_t idx = (size_t)blockIdx.x * blockDim.x + threadIdx.x; idx < tot;
         idx += (size_t)gridDim.x * blockDim.x) {
        int n = (int)(idx >> 5);
        int cc = ((int)idx & 31) << 3;
        float4 al0 = *(const float4*)(g_alpha + cc);
        float4 al1 = *(const float4*)(g_alpha + cc + 4);
        float4 be0 = *(const float4*)(g_beta + cc);
        float4 be1 = *(const float4*)(g_beta + cc + 4);
        float4 cb0 = *(const float4*)(comb + cc);
        float4 cb1 = *(const float4*)(comb + cc + 4);
        uint4 pv = *(const uint4*)(P + ((size_t)n << 8) + cc);
        float pb[8];
        {
            float2 a;
            a = uf2(pv.x); pb[0] = a.x + cb0.x; pb[1] = a.y + cb0.y;
            a = uf2(pv.y); pb[2] = a.x + cb0.z; pb[3] = a.y + cb0.w;
            a = uf2(pv.z); pb[4] = a.x + cb1.x; pb[5] = a.y + cb1.y;
            a = uf2(pv.w); pb[6] = a.x + cb1.z; pb[7] = a.y + cb1.w;
        }
        int p0 = g_seg[n], p1 = g_seg[n + 1];
        float s[8];
#pragma unroll
        for (int i = 0; i < 8; i++) s[i] = 0.f;
        for (int p = p0; p < p1; p++) {
            int sidx = g_ssrc[p];
            uint4 qv = *(const uint4*)(Qb + ((size_t)sidx << 8) + cc);
            float2 a;
            a = uf2(qv.x);
            s[0] += fmaxf(fmaf(al0.x, pb[0] + a.x, be0.x), 0.f);
            s[1] += fmaxf(fmaf(al0.y, pb[1] + a.y, be0.y), 0.f);
            a = uf2(qv.y);
            s[2] += fmaxf(fmaf(al0.z, pb[2] + a.x, be0.z), 0.f);
            s[3] += fmaxf(fmaf(al0.w, pb[3] + a.y, be0.w), 0.f);
            a = uf2(qv.z);
            s[4] += fmaxf(fmaf(al1.x, pb[4] + a.x, be1.x), 0.f);
            s[5] += fmaxf(fmaf(al1.y, pb[5] + a.y, be1.y), 0.f);
            a = uf2(qv.w);
            s[6] += fmaxf(fmaf(al1.z, pb[6] + a.x, be1.z), 0.f);
            s[7] += fmaxf(fmaf(al1.w, pb[7] + a.y, be1.w), 0.f);
        }
        float inv = g_invdeg[n];
        uint4 o;
        o.x = h2u(__floats2half2_rn(s[0] * inv, s[1] * inv));
        o.y = h2u(__floats2half2_rn(s[2] * inv, s[3] * inv));
        o.z = h2u(__floats2half2_rn(s[4] * inv, s[5] * inv));
        o.w = h2u(__floats2half2_rn(s[6] * inv, s[7] * inv));
        *(uint4*)(node + ((size_t)n << 8) + cc) = o;
    }
}

__global__ void k_pool_seg(const __half* __restrict__ h3) {
    int gph = blockIdx.x, t = threadIdx.x;
    int n0 = g_gseg[gph], n1 = g_gseg[gph + 1];
    float s = 0.f;
    for (int n = n0; n < n1; n++) s += __half2float(h3[(size_t)n * 256 + t]);
    g_pool[gph * 256 + t] = s / fmaxf((float)(n1 - n0), 1.f);
}

__global__ void k_head(const float* __restrict__ W1, const float* __restrict__ b1,
                       const float* __restrict__ W2, const float* __restrict__ b2,
                       float* __restrict__ out) {
    __shared__ float gv[256], hid[256], r0[256], r1[256];
    int r = blockIdx.x, t = threadIdx.x;
    gv[t] = g_pool[r * 256 + t];
    __syncthreads();
    float a = b1[t];
    for (int k = 0; k < 256; k++) a = fmaf(gv[k], W1[k * 256 + t], a);
    hid[t] = fmaxf(a, 0.f);
    __syncthreads();
    r0[t] = hid[t] * W2[t * 2 + 0];
    r1[t] = hid[t] * W2[t * 2 + 1];
    __syncthreads();
    for (int s = 128; s > 0; s >>= 1) {
        if (t < s) { r0[t] += r0[t + s]; r1[t] += r1[t + s]; }
        __syncthreads();
    }
    if (t == 0) {
        out[r * 2 + 0] = r0[0] + b2[0];
        out[r * 2 + 1] = r1[0] + b2[1];
    }
}

// ---------------- launcher ----------------
extern "C" void kernel_launch(void* const* d_in, const int* in_sizes, int n_in,
                              void* d_out, int out_size) {
    const float* x      = (const float*)d_in[0];
    const void*  ei     = d_in[1];
    const void*  bt     = d_in[2];
    const float* c1_w1  = (const float*)d_in[3];
    const float* c1_b1  = (const float*)d_in[4];
    const float* c1_gn1 = (const float*)d_in[5];
    const float* c1_w2  = (const float*)d_in[6];
    const float* c1_b2  = (const float*)d_in[7];
    const float* c1_gn2 = (const float*)d_in[8];
    const float* c1_w3  = (const float*)d_in[9];
    const float* c1_b3  = (const float*)d_in[10];
    const float* c1_gn3 = (const float*)d_in[11];
    const float* c2_w1  = (const float*)d_in[12];
    const float* c2_b1  = (const float*)d_in[13];
    const float* c2_gn1 = (const float*)d_in[14];
    const float* c2_w2  = (const float*)d_in[15];
    const float* c2_b2  = (const float*)d_in[16];
    const float* c2_gn2 = (const float*)d_in[17];
    const float* c3_w1  = (const float*)d_in[18];
    const float* c3_b1  = (const float*)d_in[19];
    const float* c3_gn1 = (const float*)d_in[20];
    const float* lw1    = (const float*)d_in[21];
    const float* lb1    = (const float*)d_in[22];
    const float* lw2    = (const float*)d_in[23];
    const float* lb2    = (const float*)d_in[24];
    float* out = (float*)d_out;
    (void)in_sizes; (void)n_in; (void)out_size;

    __half *pP, *pQ, *ph1, *ph2, *ph3, *pe0, *pe1;
    uint32_t *pwt, *pwtA, *pwtB;
    int *phist, *pdout, *pghist;
    cudaGetSymbolAddress((void**)&pP, g_P);
    cudaGetSymbolAddress((void**)&pQ, g_Q);
    cudaGetSymbolAddress((void**)&ph1, g_h1);
    cudaGetSymbolAddress((void**)&ph2, g_h2);
    cudaGetSymbolAddress((void**)&ph3, g_h3);
    cudaGetSymbolAddress((void**)&pe0, g_e0);
    cudaGetSymbolAddress((void**)&pe1, g_e1);
    cudaGetSymbolAddress((void**)&pwt, g_wtp);
    cudaGetSymbolAddress((void**)&pwtA, g_wtpA);
    cudaGetSymbolAddress((void**)&pwtB, g_wtpB);
    cudaGetSymbolAddress((void**)&phist, g_hist);
    cudaGetSymbolAddress((void**)&pdout, g_dout);
    cudaGetSymbolAddress((void**)&pghist, g_ghist);

    // setup
    cudaMemsetAsync(phist, 0, NN * sizeof(int));
    cudaMemsetAsync(pdout, 0, NN * sizeof(int));
    cudaMemsetAsync(pghist, 0, NG * sizeof(int));
    k_convert<<<1024, 256>>>(ei, bt);
    k_scan_nodes<<<1, 1024>>>();
    k_scan_graphs<<<1, 1024>>>();
    k_scatter<<<1024, 256>>>();

    const int ET = NE / 64;
    const int NT = (NN + 63) / 64;

    // block 1 (C=128, 3 layers)
    k_l1<<<2048, 128>>>(x, c1_w1);
    k_stats2<<<2048, 256>>>(pP, pQ, 7);
    k_finalize<<<1, 256>>>(c1_gn1, 128, c1_b1);
    k_trp<<<64, 256>>>(c1_w2, nullptr, pwt, 128, 128);
    wm_gemm<2, true, false, 1><<<ET, 256>>>(pP, pQ, pwt, nullptr, c1_b2, c1_b1, pe0, nullptr, NE, 128);
    k_finalize<<<1, 256>>>(c1_gn2, 128, nullptr);
    k_trp<<<64, 256>>>(c1_w3, nullptr, pwtA, 128, 128);
    wm_gemm<1, true, false, 1><<<ET, 256>>>(pe0, nullptr, pwtA, nullptr, c1_b3, nullptr, pe1, nullptr, NE, 128);
    k_finalize<<<1, 256>>>(c1_gn3, 128, nullptr);
    k_agg_seg<<<4096, 256>>>(pe1, ph1, 7);

    // block 2 (C=256, 2 layers); merged node GEMM pair (no stats fusion)
    k_trp<<<128, 256>>>(c2_w1, c2_w1 + 128 * 256, pwtA, 128, 256);
    k_trp<<<128, 256>>>(c2_w1 + 128 * 256, nullptr, pwtB, 128, 256);
    wm_gemm<0, false, true, 2><<<dim3(NT, 2), 256>>>(ph1, nullptr, pwtA, pwtB, nullptr, nullptr, pP, pQ, NN, 128);
    k_stats2<<<2048, 256>>>(pP, pQ, 8);
    k_finalize<<<1, 256>>>(c2_gn1, 256, c2_b1);
    k_trp<<<256, 256>>>(c2_w2, nullptr, pwt, 256, 256);
    wm_gemm<2, true, false, 2><<<ET, 256>>>(pP, pQ, pwt, nullptr, c2_b2, c2_b1, pe0, nullptr, NE, 256);
    k_finalize<<<1, 256>>>(c2_gn2, 256, nullptr);
    k_agg_seg<<<8192, 256>>>(pe0, ph2, 8);

    // block 3 (C=256, 1 layer — no edge GEMM)
    k_trp<<<256, 256>>>(c3_w1, c3_w1 + 256 * 256, pwtA, 256, 256);
    k_trp<<<256, 256>>>(c3_w1 + 256 * 256, nullptr, pwtB, 256, 256);
    wm_gemm<0, false, true, 2><<<dim3(NT, 2), 256>>>(ph2, nullptr, pwtA, pwtB, nullptr, nullptr, pP, pQ, NN, 256);
    k_stats2<<<2048, 256>>>(pP, pQ, 8);
    k_finalize<<<1, 256>>>(c3_gn1, 256, c3_b1);
    k_agg_pq_seg<<<4096, 256>>>(pP, pQ, c3_b1, ph3);

    // pool + head
    k_pool_seg<<<NG, 256>>>(ph3);
    k_head<<<NG, 256>>>(lw1, lb1, lw2, lb2, out);
}

// round 14
// speedup vs baseline: 1.3566x; 1.0657x over previous
#include <cuda_runtime.h>
#include <cuda_fp16.h>
#include <cstdint>

#define NN 100000
#define NE 400000
#define NG 1000
#define EPSV 1e-5f

__device__ __half g_P[(size_t)NN * 256];
__device__ __half g_Q[(size_t)NN * 256];
__device__ __half g_h1[(size_t)NN * 128];
__device__ __half g_h2[(size_t)NN * 256];
__device__ __half g_h3[(size_t)NN * 256];
__device__ __half g_e0[(size_t)NE * 256];
__device__ __half g_e1[(size_t)NE * 128];
__device__ int    g_src[NE];
__device__ int    g_dst[NE];
__device__ int    g_ssrc[NE];
__device__ int    g_sdst[NE];
__device__ int    g_batch[NN];
__device__ int    g_hist[NN];
__device__ int    g_dout[NN];
__device__ int    g_seg[NN + 1];
__device__ int    g_cur[NN];
__device__ int    g_ghist[NG];
__device__ int    g_gseg[NG + 1];
__device__ float  g_invdeg[NN];
__device__ double g_sum[256];
__device__ double g_sumsq[256];
__device__ float  g_alpha[256];
__device__ float  g_beta[256];
__device__ uint32_t g_wtp [2 * 8 * 2048];
__device__ uint32_t g_wtpA[2 * 8 * 2048];
__device__ uint32_t g_wtpB[2 * 8 * 2048];
__device__ float  g_pool[NG * 256];

__device__ __forceinline__ uint32_t h2u(__half2 h) { return *reinterpret_cast<uint32_t*>(&h); }
__device__ __forceinline__ __half2 u2h(uint32_t u) { return *reinterpret_cast<__half2*>(&u); }
__device__ __forceinline__ float2 uf2(uint32_t u) { return __half22float2(u2h(u)); }

__device__ __forceinline__ uint32_t aff2(uint32_t u, float ax, float ay, float bx, float by) {
    float2 f = uf2(u);
    return h2u(__floats2half2_rn(fmaxf(fmaf(ax, f.x, bx), 0.f),
                                 fmaxf(fmaf(ay, f.y, by), 0.f)));
}
__device__ __forceinline__ uint32_t aff2s(uint32_t up, uint32_t uq,
                                          float ax, float ay, float bx, float by) {
    float2 p = uf2(up), q = uf2(uq);
    return h2u(__floats2half2_rn(fmaxf(fmaf(ax, p.x + q.x, bx), 0.f),
                                 fmaxf(fmaf(ay, p.y + q.y, by), 0.f)));
}

// ---------------- convert + histograms ----------------
__global__ void k_convert(const void* __restrict__ ei, const void* __restrict__ bt) {
    __shared__ int s64;
    if (threadIdx.x == 0) {
        const unsigned long long* e = (const unsigned long long*)ei;
        int f = 1;
        for (int i = 0; i < 256; i++)
            if (e[i] >= (unsigned long long)NN) { f = 0; break; }
        s64 = f;
    }
    __syncthreads();
    const int is64 = s64;
    int i0 = blockIdx.x * blockDim.x + threadIdx.x;
    int st = gridDim.x * blockDim.x;
    for (int k = i0; k < NE; k += st) {
        int s, d;
        if (is64) {
            const long long* e = (const long long*)ei;
            s = (int)e[k]; d = (int)e[NE + k];
        } else {
            const int* e = (const int*)ei;
            s = e[k]; d = e[NE + k];
        }
        g_src[k] = s; g_dst[k] = d;
        atomicAdd(&g_hist[d], 1);
        atomicAdd(&g_dout[s], 1);
    }
    for (int k = i0; k < NN; k += st) {
        int b = is64 ? (int)((const long long*)bt)[k] : ((const int*)bt)[k];
        g_batch[k] = b;
        atomicAdd(&g_ghist[b], 1);
    }
}

__global__ void k_scan_nodes() {
    __shared__ int wsum[32];
    __shared__ int carry;
    int t = threadIdx.x, lane = t & 31, wid = t >> 5;
    if (t == 0) carry = 0;
    __syncthreads();
    for (int base = 0; base < NN; base += 1024) {
        int i = base + t;
        int v = (i < NN) ? g_hist[i] : 0;
        int x = v;
#pragma unroll
        for (int off = 1; off < 32; off <<= 1) {
            int y = __shfl_up_sync(0xFFFFFFFFu, x, off);
            if (lane >= off) x += y;
        }
        if (lane == 31) wsum[wid] = x;
        __syncthreads();
        if (wid == 0) {
            int wv = wsum[lane];
#pragma unroll
            for (int off = 1; off < 32; off <<= 1) {
                int y = __shfl_up_sync(0xFFFFFFFFu, wv, off);
                if (lane >= off) wv += y;
            }
            wsum[lane] = wv;
        }
        __syncthreads();
        int incl = x + (wid ? wsum[wid - 1] : 0);
        int c = carry;
        if (i < NN) {
            g_seg[i] = c + incl - v;
            g_cur[i] = c + incl - v;
            g_invdeg[i] = 1.f / fmaxf((float)v, 1.f);
        }
        __syncthreads();
        if (t == 1023) carry += incl;
        __syncthreads();
    }
    if (t == 0) g_seg[NN] = carry;
}

__global__ void k_scan_graphs() {
    __shared__ int sb[1024];
    int t = threadIdx.x;
    int v = (t < NG) ? g_ghist[t] : 0;
    sb[t] = v;
    __syncthreads();
    for (int off = 1; off < 1024; off <<= 1) {
        int x = sb[t];
        int y = (t >= off) ? sb[t - off] : 0;
        __syncthreads();
        sb[t] = x + y;
        __syncthreads();
    }
    if (t < NG) g_gseg[t] = sb[t] - v;
    if (t == 1023) g_gseg[NG] = sb[1023];
}

__global__ void k_scatter() {
    int i = blockIdx.x * blockDim.x + threadIdx.x;
    for (; i < NE; i += gridDim.x * blockDim.x) {
        int d = g_dst[i];
        int p = atomicAdd(&g_cur[d], 1);
        g_ssrc[p] = g_src[i];
        g_sdst[p] = d;
    }
}

// layer-1 of block 1
__global__ void k_l1(const float* __restrict__ x, const float* __restrict__ W) {
    __shared__ float wd[5 * 128], wb[5 * 128];
    int c = threadIdx.x;
#pragma unroll
    for (int k = 0; k < 5; k++) {
        float t = W[(5 + k) * 128 + c];
        wb[k * 128 + c] = t;
        wd[k * 128 + c] = W[k * 128 + c] - t;
    }
    __syncthreads();
    for (int n = blockIdx.x; n < NN; n += gridDim.x) {
        float xv[5];
#pragma unroll
        for (int k = 0; k < 5; k++) xv[k] = x[n * 5 + k];
        float p = 0.f, q = 0.f;
#pragma unroll
        for (int k = 0; k < 5; k++) {
            p = fmaf(xv[k], wd[k * 128 + c], p);
            q = fmaf(xv[k], wb[k * 128 + c], q);
        }
        g_P[(size_t)n * 128 + c] = __float2half_rn(p);
        g_Q[(size_t)n * 128 + c] = __float2half_rn(q);
    }
}

// ---- factorized edge stats, 8 channels/thread (uint4 gathers) ----
__global__ void k_stats2(const __half* __restrict__ P, const __half* __restrict__ Qb, int logC) {
    __shared__ float Ss[256], Sq[256];
    const int opn = 1 << (logC - 3);
    const int t = threadIdx.x;
    const int nlane = t >> (logC - 3);
    const int npb = 256 >> (logC - 3);
    const int cc = (t & (opn - 1)) << 3;
    if (t < (1 << logC)) { Ss[t] = 0.f; Sq[t] = 0.f; }

    float s[8], q[8];
#pragma unroll
    for (int i = 0; i < 8; i++) { s[i] = 0.f; q[i] = 0.f; }

    const int ngroups = (NN + npb - 1) / npb;
    for (int ng = blockIdx.x; ng < ngroups; ng += gridDim.x) {
        int n = ng * npb + nlane;
        if (n >= NN) continue;
        int p0 = g_seg[n], p1 = g_seg[n + 1];
        float din = (float)(p1 - p0);
        float dout = (float)g_dout[n];
        uint4 pv = *(const uint4*)(P + ((size_t)n << logC) + cc);
        uint4 qv = *(const uint4*)(Qb + ((size_t)n << logC) + cc);
        float pf[8], qf[8];
        {
            float2 a;
            a = uf2(pv.x); pf[0] = a.x; pf[1] = a.y;
            a = uf2(pv.y); pf[2] = a.x; pf[3] = a.y;
            a = uf2(pv.z); pf[4] = a.x; pf[5] = a.y;
            a = uf2(pv.w); pf[6] = a.x; pf[7] = a.y;
            a = uf2(qv.x); qf[0] = a.x; qf[1] = a.y;
            a = uf2(qv.y); qf[2] = a.x; qf[3] = a.y;
            a = uf2(qv.z); qf[4] = a.x; qf[5] = a.y;
            a = uf2(qv.w); qf[6] = a.x; qf[7] = a.y;
        }
        float r[8];
#pragma unroll
        for (int i = 0; i < 8; i++) r[i] = 0.f;
        for (int p = p0; p < p1; p++) {
            int sidx = g_ssrc[p];
            uint4 sv = *(const uint4*)(Qb + ((size_t)sidx << logC) + cc);
            float2 a;
            a = uf2(sv.x); r[0] += a.x; r[1] += a.y;
            a = uf2(sv.y); r[2] += a.x; r[3] += a.y;
            a = uf2(sv.z); r[4] += a.x; r[5] += a.y;
            a = uf2(sv.w); r[6] += a.x; r[7] += a.y;
        }
#pragma unroll
        for (int i = 0; i < 8; i++) {
            s[i] += din * pf[i] + dout * qf[i];
            q[i] += din * pf[i] * pf[i] + dout * qf[i] * qf[i] + 2.f * pf[i] * r[i];
        }
    }
    __syncthreads();
#pragma unroll
    for (int i = 0; i < 8; i++) {
        atomicAdd(&Ss[cc + i], s[i]);
        atomicAdd(&Sq[cc + i], q[i]);
    }
    __syncthreads();
    if (t < (1 << logC)) {
        atomicAdd(&g_sum[t], (double)Ss[t]);
        atomicAdd(&g_sumsq[t], (double)Sq[t]);
    }
}

__global__ void k_finalize(const float* __restrict__ gn, int C, const float* __restrict__ comb) {
    int c = threadIdx.x;
    if (c < C) {
        double s = g_sum[c], q = g_sumsq[c];
        if (comb) {
            double bc = (double)comb[c];
            q += 2.0 * bc * s + (double)NE * bc * bc;
            s += (double)NE * bc;
        }
        float invE = 1.f / (float)NE;
        float m  = (float)(s * invE);
        float m2 = (float)(q * invE);
        float g = gn[c], b = gn[C + c], ms = gn[2 * C + c];
        float var = m2 - 2.f * ms * m * m + ms * ms * m * m;
        float rs = rsqrtf(var + EPSV);
        g_alpha[c] = g * rs;
        g_beta[c]  = b - g * rs * ms * m;
        g_sum[c] = 0.0;
        g_sumsq[c] = 0.0;
    }
}

// pre-permute weights into mma B-fragment layout
__global__ void k_trp(const float* __restrict__ Wa, const float* __restrict__ Wb,
                      uint32_t* __restrict__ out, int K, int N) {
    int tot = N * (K >> 1);
    int i = blockIdx.x * blockDim.x + threadIdx.x;
    for (; i < tot; i += gridDim.x * blockDim.x) {
        int n = i / (K >> 1);
        int kp = i - n * (K >> 1);
        int k = kp << 1;
        float v0 = Wa[(size_t)k * N + n], v1 = Wa[(size_t)(k + 1) * N + n];
        if (Wb) { v0 -= Wb[(size_t)k * N + n]; v1 -= Wb[(size_t)(k + 1) * N + n]; }
        int ch = k >> 5;
        int kpair = (k >> 1) & 15;
        int ksP = kpair >> 3, khi8 = (kpair >> 2) & 1, t4P = kpair & 3;
        int nblk = n >> 7, r = n & 127;
        int ni = r & 31, wn = r >> 5, nf = ni >> 3, gB = ni & 7;
        int slot = ((((wn << 1) + ksP) << 2) + nf) * 64 + (gB << 3) + (t4P << 1) + khi8;
        out[((size_t)nblk * (K >> 5) + ch) * 2048 + slot] = h2u(__floats2half2_rn(v0, v1));
    }
}

// ---------------- fp16 mma GEMM (unified; THREADS=256 for NB=1, 512 for NB=2) ----
// MODE 0: plain half A. MODE 1: relu(affine(A)). MODE 2: relu(affine(P[sdst]+Q[ssrc]+comb))
// STATS: per-channel sum/sumsq. PAIR: blockIdx.y selects (Bp,Co)/(Bp2,Co2).
// Warp layout: warpM = w&1 (2x32 rows), warpN = w>>1 (THREADS/64 N-slices of 32).
// Producers = warps 0-7 (stage A tile); all warps consume.
template <int MODE, bool STATS, bool PAIR, int NB, int THREADS>
__global__ void __launch_bounds__(THREADS, 2)
wm_gemm(const __half* __restrict__ A, const __half* __restrict__ Qb,
        const uint32_t* __restrict__ Bp, const uint32_t* __restrict__ Bp2,
        const float* __restrict__ bias, const float* __restrict__ comb,
        __half* __restrict__ Co, __half* __restrict__ Co2,
        int M, int K) {
    __shared__ uint32_t sAu[2][1024];
    __shared__ float Ssum[NB * 128], Ssq[NB * 128];
    const int N = NB * 128;
    const int tid = threadIdx.x;
    const int w = tid >> 5, lane = tid & 31;
    const int g = lane >> 2, t4 = lane & 3;
    const int warpM = w & 1, warpN = w >> 1;
    const int nb = warpN >> 2, wn = warpN & 3;
    const int m0 = blockIdx.x * 64;
    const bool prod = (w < 8);
    const uint32_t* Bu = (PAIR && blockIdx.y) ? Bp2 : Bp;
    __half* Cu = (PAIR && blockIdx.y) ? Co2 : Co;

    if (STATS) {
#pragma unroll
        for (int i = tid; i < NB * 128; i += THREADS) { Ssum[i] = 0.f; Ssq[i] = 0.f; }
    }

    float c[2][4][4];
#pragma unroll
    for (int i = 0; i < 2; i++)
#pragma unroll
        for (int j = 0; j < 4; j++)
#pragma unroll
            for (int k = 0; k < 4; k++) c[i][j][k] = 0.f;

    const int rowlane = lane >> 2, kq8 = lane & 3;
    const int r = ((w & 7) << 3) + rowlane;
    const int gm = m0 + r;
    const bool valid = prod && (gm < M);
    int rd = 0, rs = 0;
    if (MODE == 2) { rd = valid ? g_sdst[gm] : 0; rs = valid ? g_ssrc[gm] : 0; }
    int slotk[4];
    {
        const int wm = r >> 5, ri = r & 31, mf = ri >> 4, rb = ri & 15;
        const int gA = rb & 7, rowhi = rb >> 3;
        const int ksP = kq8 >> 1, khi8 = kq8 & 1;
#pragma unroll
        for (int i = 0; i < 4; i++)
            slotk[i] = ((((wm << 1) + ksP) << 1) + mf) * 128 + (gA << 4) + (i << 2) + rowhi + (khi8 << 1);
    }
    const int nch = K >> 5;

    auto load_regs = [&](int ch, uint32_t* hu) {
        const int cg = (ch << 5) + (kq8 << 3);
        if (!valid) { hu[0] = hu[1] = hu[2] = hu[3] = 0; return; }
        if (MODE == 0) {
            uint4 v = *(const uint4*)(A + (size_t)gm * K + cg);
            hu[0] = v.x; hu[1] = v.y; hu[2] = v.z; hu[3] = v.w;
            return;
        }
        float4 al0 = *(const float4*)(g_alpha + cg);
        float4 al1 = *(const float4*)(g_alpha + cg + 4);
        float4 be0 = *(const float4*)(g_beta + cg);
        float4 be1 = *(const float4*)(g_beta + cg + 4);
        if (MODE == 2) {
            float4 cb0 = *(const float4*)(comb + cg);
            float4 cb1 = *(const float4*)(comb + cg + 4);
            be0.x = fmaf(al0.x, cb0.x, be0.x); be0.y = fmaf(al0.y, cb0.y, be0.y);
            be0.z = fmaf(al0.z, cb0.z, be0.z); be0.w = fmaf(al0.w, cb0.w, be0.w);
            be1.x = fmaf(al1.x, cb1.x, be1.x); be1.y = fmaf(al1.y, cb1.y, be1.y);
            be1.z = fmaf(al1.z, cb1.z, be1.z); be1.w = fmaf(al1.w, cb1.w, be1.w);
        }
        if (MODE == 1) {
            uint4 v = *(const uint4*)(A + (size_t)gm * K + cg);
            hu[0] = aff2(v.x, al0.x, al0.y, be0.x, be0.y);
            hu[1] = aff2(v.y, al0.z, al0.w, be0.z, be0.w);
            hu[2] = aff2(v.z, al1.x, al1.y, be1.x, be1.y);
            hu[3] = aff2(v.w, al1.z, al1.w, be1.z, be1.w);
        } else {
            uint4 pv = *(const uint4*)(A + (size_t)rd * K + cg);
            uint4 qv = *(const uint4*)(Qb + (size_t)rs * K + cg);
            hu[0] = aff2s(pv.x, qv.x, al0.x, al0.y, be0.x, be0.y);
            hu[1] = aff2s(pv.y, qv.y, al0.z, al0.w, be0.z, be0.w);
            hu[2] = aff2s(pv.z, qv.z, al1.x, al1.y, be1.x, be1.y);
            hu[3] = aff2s(pv.w, qv.w, al1.z, al1.w, be1.z, be1.w);
        }
    };

    if (prod) {
        uint32_t hu[4];
        load_regs(0, hu);
#pragma unroll
        for (int j = 0; j < 4; j++) sAu[0][slotk[j]] = hu[j];
    }
    __syncthreads();

    for (int ch = 0; ch < nch; ch++) {
        uint32_t hn[4];
        if (prod && ch + 1 < nch) load_regs(ch + 1, hn);

        const uint4* A4 = (const uint4*)sAu[ch & 1];
        const uint2* B2 = (const uint2*)(Bu + ((size_t)nb * nch + ch) * 2048);
#pragma unroll
        for (int ks = 0; ks < 2; ks++) {
            uint4 af[2];
#pragma unroll
            for (int mf = 0; mf < 2; mf++)
                af[mf] = A4[((((warpM << 1) + ks) << 1) + mf) * 32 + lane];
            uint2 bf[4];
#pragma unroll
            for (int nf = 0; nf < 4; nf++)
                bf[nf] = B2[((((wn << 1) + ks) << 2) + nf) * 32 + lane];
#pragma unroll
            for (int mf = 0; mf < 2; mf++)
#pragma unroll
                for (int nf = 0; nf < 4; nf++) {
                    asm volatile(
                        "mma.sync.aligned.m16n8k16.row.col.f32.f16.f16.f32 "
                        "{%0,%1,%2,%3}, {%4,%5,%6,%7}, {%8,%9}, {%0,%1,%2,%3};"
                        : "+f"(c[mf][nf][0]), "+f"(c[mf][nf][1]),
                          "+f"(c[mf][nf][2]), "+f"(c[mf][nf][3])
                        : "r"(af[mf].x), "r"(af[mf].y), "r"(af[mf].z), "r"(af[mf].w),
                          "r"(bf[nf].x), "r"(bf[nf].y));
                }
        }
        if (prod && ch + 1 < nch) {
#pragma unroll
            for (int j = 0; j < 4; j++) sAu[(ch + 1) & 1][slotk[j]] = hn[j];
        }
        __syncthreads();
    }

#pragma unroll
    for (int mf = 0; mf < 2; mf++) {
        int r0 = m0 + warpM * 32 + mf * 16 + g;
#pragma unroll
        for (int nf = 0; nf < 4; nf++) {
            int colL = nb * 128 + wn * 32 + nf * 8 + 2 * t4;
            float b0 = bias ? bias[colL] : 0.f;
            float b1 = bias ? bias[colL + 1] : 0.f;
            float v0 = c[mf][nf][0] + b0, v1 = c[mf][nf][1] + b1;
            float v2 = c[mf][nf][2] + b0, v3 = c[mf][nf][3] + b1;
            if (r0 < M)
                *(__half2*)(Cu + (size_t)r0 * N + colL) = __floats2half2_rn(v0, v1);
            if (r0 + 8 < M)
                *(__half2*)(Cu + (size_t)(r0 + 8) * N + colL) = __floats2half2_rn(v2, v3);
            if (STATS) {
                atomicAdd(&Ssum[colL], v0 + v2);
                atomicAdd(&Ssum[colL + 1], v1 + v3);
                atomicAdd(&Ssq[colL], fmaf(v0, v0, v2 * v2));
                atomicAdd(&Ssq[colL + 1], fmaf(v1, v1, v3 * v3));
            }
        }
    }
    if (STATS) {
        __syncthreads();
#pragma unroll
        for (int i = tid; i < NB * 128; i += THREADS) {
            atomicAdd(&g_sum[i], (double)Ssum[i]);
            atomicAdd(&g_sumsq[i], (double)Ssq[i]);
        }
    }
}

// ---------------- segment-reduce aggregations (8 ch/thread) ----------------
__global__ void k_agg_seg(const __half* __restrict__ H, __half* __restrict__ node, int logC) {
    const int sh = logC - 3;
    size_t tot = (size_t)NN << sh;
    for (size_t idx = (size_t)blockIdx.x * blockDim.x + threadIdx.x; idx < tot;
         idx += (size_t)gridDim.x * blockDim.x) {
        int n = (int)(idx >> sh);
        int cc = ((int)idx & ((1 << sh) - 1)) << 3;
        float4 al0 = *(const float4*)(g_alpha + cc);
        float4 al1 = *(const float4*)(g_alpha + cc + 4);
        float4 be0 = *(const float4*)(g_beta + cc);
        float4 be1 = *(const float4*)(g_beta + cc + 4);
        int p0 = g_seg[n], p1 = g_seg[n + 1];
        float s[8];
#pragma unroll
        for (int i = 0; i < 8; i++) s[i] = 0.f;
        for (int p = p0; p < p1; p++) {
            uint4 hv = *(const uint4*)(H + ((size_t)p << logC) + cc);
            float2 a;
            a = uf2(hv.x);
            s[0] += fmaxf(fmaf(al0.x, a.x, be0.x), 0.f);
            s[1] += fmaxf(fmaf(al0.y, a.y, be0.y), 0.f);
            a = uf2(hv.y);
            s[2] += fmaxf(fmaf(al0.z, a.x, be0.z), 0.f);
            s[3] += fmaxf(fmaf(al0.w, a.y, be0.w), 0.f);
            a = uf2(hv.z);
            s[4] += fmaxf(fmaf(al1.x, a.x, be1.x), 0.f);
            s[5] += fmaxf(fmaf(al1.y, a.y, be1.y), 0.f);
            a = uf2(hv.w);
            s[6] += fmaxf(fmaf(al1.z, a.x, be1.z), 0.f);
            s[7] += fmaxf(fmaf(al1.w, a.y, be1.w), 0.f);
        }
        float inv = g_invdeg[n];
        uint4 o;
        o.x = h2u(__floats2half2_rn(s[0] * inv, s[1] * inv));
        o.y = h2u(__floats2half2_rn(s[2] * inv, s[3] * inv));
        o.z = h2u(__floats2half2_rn(s[4] * inv, s[5] * inv));
        o.w = h2u(__floats2half2_rn(s[6] * inv, s[7] * inv));
        *(uint4*)(node + ((size_t)n << logC) + cc) = o;
    }
}

__global__ void k_agg_pq_seg(const __half* __restrict__ P, const __half* __restrict__ Qb,
                             const float* __restrict__ comb, __half* __restrict__ node) {
    size_t tot = (size_t)NN * 32;
    for (size_t idx = (size_t)blockIdx.x * blockDim.x + threadIdx.x; idx < tot;
         idx += (size_t)gridDim.x * blockDim.x) {
        int n = (int)(idx >> 5);
        int cc = ((int)idx & 31) << 3;
        float4 al0 = *(const float4*)(g_alpha + cc);
        float4 al1 = *(const float4*)(g_alpha + cc + 4);
        float4 be0 = *(const float4*)(g_beta + cc);
        float4 be1 = *(const float4*)(g_beta + cc + 4);
        float4 cb0 = *(const float4*)(comb + cc);
        float4 cb1 = *(const float4*)(comb + cc + 4);
        uint4 pv = *(const uint4*)(P + ((size_t)n << 8) + cc);
        float pb[8];
        {
            float2 a;
            a = uf2(pv.x); pb[0] = a.x + cb0.x; pb[1] = a.y + cb0.y;
            a = uf2(pv.y); pb[2] = a.x + cb0.z; pb[3] = a.y + cb0.w;
            a = uf2(pv.z); pb[4] = a.x + cb1.x; pb[5] = a.y + cb1.y;
            a = uf2(pv.w); pb[6] = a.x + cb1.z; pb[7] = a.y + cb1.w;
        }
        int p0 = g_seg[n], p1 = g_seg[n + 1];
        float s[8];
#pragma unroll
        for (int i = 0; i < 8; i++) s[i] = 0.f;
        for (int p = p0; p < p1; p++) {
            int sidx = g_ssrc[p];
            uint4 qv = *(const uint4*)(Qb + ((size_t)sidx << 8) + cc);
            float2 a;
            a = uf2(qv.x);
            s[0] += fmaxf(fmaf(al0.x, pb[0] + a.x, be0.x), 0.f);
            s[1] += fmaxf(fmaf(al0.y, pb[1] + a.y, be0.y), 0.f);
            a = uf2(qv.y);
            s[2] += fmaxf(fmaf(al0.z, pb[2] + a.x, be0.z), 0.f);
            s[3] += fmaxf(fmaf(al0.w, pb[3] + a.y, be0.w), 0.f);
            a = uf2(qv.z);
            s[4] += fmaxf(fmaf(al1.x, pb[4] + a.x, be1.x), 0.f);
            s[5] += fmaxf(fmaf(al1.y, pb[5] + a.y, be1.y), 0.f);
            a = uf2(qv.w);
            s[6] += fmaxf(fmaf(al1.z, pb[6] + a.x, be1.z), 0.f);
            s[7] += fmaxf(fmaf(al1.w, pb[7] + a.y, be1.w), 0.f);
        }
        float inv = g_invdeg[n];
        uint4 o;
        o.x = h2u(__floats2half2_rn(s[0] * inv, s[1] * inv));
        o.y = h2u(__floats2half2_rn(s[2] * inv, s[3] * inv));
        o.z = h2u(__floats2half2_rn(s[4] * inv, s[5] * inv));
        o.w = h2u(__floats2half2_rn(s[6] * inv, s[7] * inv));
        *(uint4*)(node + ((size_t)n << 8) + cc) = o;
    }
}

__global__ void k_pool_seg(const __half* __restrict__ h3) {
    int gph = blockIdx.x, t = threadIdx.x;
    int n0 = g_gseg[gph], n1 = g_gseg[gph + 1];
    float s = 0.f;
    for (int n = n0; n < n1; n++) s += __half2float(h3[(size_t)n * 256 + t]);
    g_pool[gph * 256 + t] = s / fmaxf((float)(n1 - n0), 1.f);
}

__global__ void k_head(const float* __restrict__ W1, const float* __restrict__ b1,
                       const float* __restrict__ W2, const float* __restrict__ b2,
                       float* __restrict__ out) {
    __shared__ float gv[256], hid[256], r0[256], r1[256];
    int r = blockIdx.x, t = threadIdx.x;
    gv[t] = g_pool[r * 256 + t];
    __syncthreads();
    float a = b1[t];
    for (int k = 0; k < 256; k++) a = fmaf(gv[k], W1[k * 256 + t], a);
    hid[t] = fmaxf(a, 0.f);
    __syncthreads();
    r0[t] = hid[t] * W2[t * 2 + 0];
    r1[t] = hid[t] * W2[t * 2 + 1];
    __syncthreads();
    for (int s = 128; s > 0; s >>= 1) {
        if (t < s) { r0[t] += r0[t + s]; r1[t] += r1[t + s]; }
        __syncthreads();
    }
    if (t == 0) {
        out[r * 2 + 0] = r0[0] + b2[0];
        out[r * 2 + 1] = r1[0] + b2[1];
    }
}

// ---------------- launcher ----------------
extern "C" void kernel_launch(void* const* d_in, const int* in_sizes, int n_in,
                              void* d_out, int out_size) {
    const float* x      = (const float*)d_in[0];
    const void*  ei     = d_in[1];
    const void*  bt     = d_in[2];
    const float* c1_w1  = (const float*)d_in[3];
    const float* c1_b1  = (const float*)d_in[4];
    const float* c1_gn1 = (const float*)d_in[5];
    const float* c1_w2  = (const float*)d_in[6];
    const float* c1_b2  = (const float*)d_in[7];
    const float* c1_gn2 = (const float*)d_in[8];
    const float* c1_w3  = (const float*)d_in[9];
    const float* c1_b3  = (const float*)d_in[10];
    const float* c1_gn3 = (const float*)d_in[11];
    const float* c2_w1  = (const float*)d_in[12];
    const float* c2_b1  = (const float*)d_in[13];
    const float* c2_gn1 = (const float*)d_in[14];
    const float* c2_w2  = (const float*)d_in[15];
    const float* c2_b2  = (const float*)d_in[16];
    const float* c2_gn2 = (const float*)d_in[17];
    const float* c3_w1  = (const float*)d_in[18];
    const float* c3_b1  = (const float*)d_in[19];
    const float* c3_gn1 = (const float*)d_in[20];
    const float* lw1    = (const float*)d_in[21];
    const float* lb1    = (const float*)d_in[22];
    const float* lw2    = (const float*)d_in[23];
    const float* lb2    = (const float*)d_in[24];
    float* out = (float*)d_out;
    (void)in_sizes; (void)n_in; (void)out_size;

    __half *pP, *pQ, *ph1, *ph2, *ph3, *pe0, *pe1;
    uint32_t *pwt, *pwtA, *pwtB;
    int *phist, *pdout, *pghist;
    cudaGetSymbolAddress((void**)&pP, g_P);
    cudaGetSymbolAddress((void**)&pQ, g_Q);
    cudaGetSymbolAddress((void**)&ph1, g_h1);
    cudaGetSymbolAddress((void**)&ph2, g_h2);
    cudaGetSymbolAddress((void**)&ph3, g_h3);
    cudaGetSymbolAddress((void**)&pe0, g_e0);
    cudaGetSymbolAddress((void**)&pe1, g_e1);
    cudaGetSymbolAddress((void**)&pwt, g_wtp);
    cudaGetSymbolAddress((void**)&pwtA, g_wtpA);
    cudaGetSymbolAddress((void**)&pwtB, g_wtpB);
    cudaGetSymbolAddress((void**)&phist, g_hist);
    cudaGetSymbolAddress((void**)&pdout, g_dout);
    cudaGetSymbolAddress((void**)&pghist, g_ghist);

    // setup
    cudaMemsetAsync(phist, 0, NN * sizeof(int));
    cudaMemsetAsync(pdout, 0, NN * sizeof(int));
    cudaMemsetAsync(pghist, 0, NG * sizeof(int));
    k_convert<<<1024, 256>>>(ei, bt);
    k_scan_nodes<<<1, 1024>>>();
    k_scan_graphs<<<1, 1024>>>();
    k_scatter<<<1024, 256>>>();

    const int ET = NE / 64;
    const int NT = (NN + 63) / 64;

    // block 1 (C=128, 3 layers) — NB=1, 256 threads
    k_l1<<<2048, 128>>>(x, c1_w1);
    k_stats2<<<2048, 256>>>(pP, pQ, 7);
    k_finalize<<<1, 256>>>(c1_gn1, 128, c1_b1);
    k_trp<<<64, 256>>>(c1_w2, nullptr, pwt, 128, 128);
    wm_gemm<2, true, false, 1, 256><<<ET, 256>>>(pP, pQ, pwt, nullptr, c1_b2, c1_b1, pe0, nullptr, NE, 128);
    k_finalize<<<1, 256>>>(c1_gn2, 128, nullptr);
    k_trp<<<64, 256>>>(c1_w3, nullptr, pwtA, 128, 128);
    wm_gemm<1, true, false, 1, 256><<<ET, 256>>>(pe0, nullptr, pwtA, nullptr, c1_b3, nullptr, pe1, nullptr, NE, 128);
    k_finalize<<<1, 256>>>(c1_gn3, 128, nullptr);
    k_agg_seg<<<4096, 256>>>(pe1, ph1, 7);

    // block 2 (C=256, 2 layers) — NB=2, 512 threads
    k_trp<<<128, 256>>>(c2_w1, c2_w1 + 128 * 256, pwtA, 128, 256);
    k_trp<<<128, 256>>>(c2_w1 + 128 * 256, nullptr, pwtB, 128, 256);
    wm_gemm<0, false, true, 2, 512><<<dim3(NT, 2), 512>>>(ph1, nullptr, pwtA, pwtB, nullptr, nullptr, pP, pQ, NN, 128);
    k_stats2<<<2048, 256>>>(pP, pQ, 8);
    k_finalize<<<1, 256>>>(c2_gn1, 256, c2_b1);
    k_trp<<<256, 256>>>(c2_w2, nullptr, pwt, 256, 256);
    wm_gemm<2, true, false, 2, 512><<<ET, 512>>>(pP, pQ, pwt, nullptr, c2_b2, c2_b1, pe0, nullptr, NE, 256);
    k_finalize<<<1, 256>>>(c2_gn2, 256, nullptr);
    k_agg_seg<<<8192, 256>>>(pe0, ph2, 8);

    // block 3 (C=256, 1 layer — no edge GEMM)
    k_trp<<<256, 256>>>(c3_w1, c3_w1 + 256 * 256, pwtA, 256, 256);
    k_trp<<<256, 256>>>(c3_w1 + 256 * 256, nullptr, pwtB, 256, 256);
    wm_gemm<0, false, true, 2, 512><<<dim3(NT, 2), 512>>>(ph2, nullptr, pwtA, pwtB, nullptr, nullptr, pP, pQ, NN, 256);
    k_stats2<<<2048, 256>>>(pP, pQ, 8);
    k_finalize<<<1, 256>>>(c3_gn1, 256, c3_b1);
    k_agg_pq_seg<<<4096, 256>>>(pP, pQ, c3_b1, ph3);

    // pool + head
    k_pool_seg<<<NG, 256>>>(ph3);
    k_head<<<NG, 256>>>(lw1, lb1, lw2, lb2, out);
}

// round 15
// speedup vs baseline: 1.4950x; 1.1021x over previous
#include <cuda_runtime.h>
#include <cuda_fp16.h>
#include <cstdint>

#define NN 100000
#define NE 400000
#define NG 1000
#define EPSV 1e-5f

__device__ __half g_P[(size_t)NN * 256];
__device__ __half g_Q[(size_t)NN * 256];
__device__ __half g_h1[(size_t)NN * 128];
__device__ __half g_h2[(size_t)NN * 256];
__device__ __half g_h3[(size_t)NN * 256];
__device__ __half g_e0[(size_t)NE * 256];
__device__ __half g_e1[(size_t)NE * 128];
__device__ int    g_src[NE];
__device__ int    g_dst[NE];
__device__ int    g_ssrc[NE];
__device__ int    g_sdst[NE];
__device__ int    g_batch[NN];
__device__ int    g_hist[NN];
__device__ int    g_dout[NN];
__device__ int    g_seg[NN + 1];
__device__ int    g_cur[NN];
__device__ int    g_ghist[NG];
__device__ int    g_gseg[NG + 1];
__device__ float  g_invdeg[NN];
__device__ double g_sum[256];
__device__ double g_sumsq[256];
__device__ float  g_alpha[256];
__device__ float  g_beta[256];
__device__ uint32_t g_wtp [2 * 8 * 2048];
__device__ uint32_t g_wtpA[2 * 8 * 2048];
__device__ uint32_t g_wtpB[2 * 8 * 2048];
__device__ float  g_pool[NG * 256];

__device__ __forceinline__ uint32_t h2u(__half2 h) { return *reinterpret_cast<uint32_t*>(&h); }
__device__ __forceinline__ __half2 u2h(uint32_t u) { return *reinterpret_cast<__half2*>(&u); }
__device__ __forceinline__ float2 uf2(uint32_t u) { return __half22float2(u2h(u)); }

__device__ __forceinline__ uint32_t aff2(uint32_t u, float ax, float ay, float bx, float by) {
    float2 f = uf2(u);
    return h2u(__floats2half2_rn(fmaxf(fmaf(ax, f.x, bx), 0.f),
                                 fmaxf(fmaf(ay, f.y, by), 0.f)));
}
__device__ __forceinline__ uint32_t aff2s(uint32_t up, uint32_t uq,
                                          float ax, float ay, float bx, float by) {
    float2 p = uf2(up), q = uf2(uq);
    return h2u(__floats2half2_rn(fmaxf(fmaf(ax, p.x + q.x, bx), 0.f),
                                 fmaxf(fmaf(ay, p.y + q.y, by), 0.f)));
}

// ---------------- convert + histograms ----------------
__global__ void k_convert(const void* __restrict__ ei, const void* __restrict__ bt) {
    __shared__ int s64;
    if (threadIdx.x == 0) {
        const unsigned long long* e = (const unsigned long long*)ei;
        int f = 1;
        for (int i = 0; i < 256; i++)
            if (e[i] >= (unsigned long long)NN) { f = 0; break; }
        s64 = f;
    }
    __syncthreads();
    const int is64 = s64;
    int i0 = blockIdx.x * blockDim.x + threadIdx.x;
    int st = gridDim.x * blockDim.x;
    for (int k = i0; k < NE; k += st) {
        int s, d;
        if (is64) {
            const long long* e = (const long long*)ei;
            s = (int)e[k]; d = (int)e[NE + k];
        } else {
            const int* e = (const int*)ei;
            s = e[k]; d = e[NE + k];
        }
        g_src[k] = s; g_dst[k] = d;
        atomicAdd(&g_hist[d], 1);
        atomicAdd(&g_dout[s], 1);
    }
    for (int k = i0; k < NN; k += st) {
        int b = is64 ? (int)((const long long*)bt)[k] : ((const int*)bt)[k];
        g_batch[k] = b;
        atomicAdd(&g_ghist[b], 1);
    }
}

__global__ void k_scan_nodes() {
    __shared__ int wsum[32];
    __shared__ int carry;
    int t = threadIdx.x, lane = t & 31, wid = t >> 5;
    if (t == 0) carry = 0;
    __syncthreads();
    for (int base = 0; base < NN; base += 1024) {
        int i = base + t;
        int v = (i < NN) ? g_hist[i] : 0;
        int x = v;
#pragma unroll
        for (int off = 1; off < 32; off <<= 1) {
            int y = __shfl_up_sync(0xFFFFFFFFu, x, off);
            if (lane >= off) x += y;
        }
        if (lane == 31) wsum[wid] = x;
        __syncthreads();
        if (wid == 0) {
            int wv = wsum[lane];
#pragma unroll
            for (int off = 1; off < 32; off <<= 1) {
                int y = __shfl_up_sync(0xFFFFFFFFu, wv, off);
                if (lane >= off) wv += y;
            }
            wsum[lane] = wv;
        }
        __syncthreads();
        int incl = x + (wid ? wsum[wid - 1] : 0);
        int c = carry;
        if (i < NN) {
            g_seg[i] = c + incl - v;
            g_cur[i] = c + incl - v;
            g_invdeg[i] = 1.f / fmaxf((float)v, 1.f);
        }
        __syncthreads();
        if (t == 1023) carry += incl;
        __syncthreads();
    }
    if (t == 0) g_seg[NN] = carry;
}

__global__ void k_scan_graphs() {
    __shared__ int sb[1024];
    int t = threadIdx.x;
    int v = (t < NG) ? g_ghist[t] : 0;
    sb[t] = v;
    __syncthreads();
    for (int off = 1; off < 1024; off <<= 1) {
        int x = sb[t];
        int y = (t >= off) ? sb[t - off] : 0;
        __syncthreads();
        sb[t] = x + y;
        __syncthreads();
    }
    if (t < NG) g_gseg[t] = sb[t] - v;
    if (t == 1023) g_gseg[NG] = sb[1023];
}

__global__ void k_scatter() {
    int i = blockIdx.x * blockDim.x + threadIdx.x;
    for (; i < NE; i += gridDim.x * blockDim.x) {
        int d = g_dst[i];
        int p = atomicAdd(&g_cur[d], 1);
        g_ssrc[p] = g_src[i];
        g_sdst[p] = d;
    }
}

// layer-1 of block 1
__global__ void k_l1(const float* __restrict__ x, const float* __restrict__ W) {
    __shared__ float wd[5 * 128], wb[5 * 128];
    int c = threadIdx.x;
#pragma unroll
    for (int k = 0; k < 5; k++) {
        float t = W[(5 + k) * 128 + c];
        wb[k * 128 + c] = t;
        wd[k * 128 + c] = W[k * 128 + c] - t;
    }
    __syncthreads();
    for (int n = blockIdx.x; n < NN; n += gridDim.x) {
        float xv[5];
#pragma unroll
        for (int k = 0; k < 5; k++) xv[k] = x[n * 5 + k];
        float p = 0.f, q = 0.f;
#pragma unroll
        for (int k = 0; k < 5; k++) {
            p = fmaf(xv[k], wd[k * 128 + c], p);
            q = fmaf(xv[k], wb[k * 128 + c], q);
        }
        g_P[(size_t)n * 128 + c] = __float2half_rn(p);
        g_Q[(size_t)n * 128 + c] = __float2half_rn(q);
    }
}

// ---- factorized edge stats, 8 channels/thread (uint4 gathers) ----
__global__ void k_stats2(const __half* __restrict__ P, const __half* __restrict__ Qb, int logC) {
    __shared__ float Ss[256], Sq[256];
    const int opn = 1 << (logC - 3);
    const int t = threadIdx.x;
    const int nlane = t >> (logC - 3);
    const int npb = 256 >> (logC - 3);
    const int cc = (t & (opn - 1)) << 3;
    if (t < (1 << logC)) { Ss[t] = 0.f; Sq[t] = 0.f; }

    float s[8], q[8];
#pragma unroll
    for (int i = 0; i < 8; i++) { s[i] = 0.f; q[i] = 0.f; }

    const int ngroups = (NN + npb - 1) / npb;
    for (int ng = blockIdx.x; ng < ngroups; ng += gridDim.x) {
        int n = ng * npb + nlane;
        if (n >= NN) continue;
        int p0 = g_seg[n], p1 = g_seg[n + 1];
        float din = (float)(p1 - p0);
        float dout = (float)g_dout[n];
        uint4 pv = *(const uint4*)(P + ((size_t)n << logC) + cc);
        uint4 qv = *(const uint4*)(Qb + ((size_t)n << logC) + cc);
        float pf[8], qf[8];
        {
            float2 a;
            a = uf2(pv.x); pf[0] = a.x; pf[1] = a.y;
            a = uf2(pv.y); pf[2] = a.x; pf[3] = a.y;
            a = uf2(pv.z); pf[4] = a.x; pf[5] = a.y;
            a = uf2(pv.w); pf[6] = a.x; pf[7] = a.y;
            a = uf2(qv.x); qf[0] = a.x; qf[1] = a.y;
            a = uf2(qv.y); qf[2] = a.x; qf[3] = a.y;
            a = uf2(qv.z); qf[4] = a.x; qf[5] = a.y;
            a = uf2(qv.w); qf[6] = a.x; qf[7] = a.y;
        }
        float r[8];
#pragma unroll
        for (int i = 0; i < 8; i++) r[i] = 0.f;
        for (int p = p0; p < p1; p++) {
            int sidx = g_ssrc[p];
            uint4 sv = *(const uint4*)(Qb + ((size_t)sidx << logC) + cc);
            float2 a;
            a = uf2(sv.x); r[0] += a.x; r[1] += a.y;
            a = uf2(sv.y); r[2] += a.x; r[3] += a.y;
            a = uf2(sv.z); r[4] += a.x; r[5] += a.y;
            a = uf2(sv.w); r[6] += a.x; r[7] += a.y;
        }
#pragma unroll
        for (int i = 0; i < 8; i++) {
            s[i] += din * pf[i] + dout * qf[i];
            q[i] += din * pf[i] * pf[i] + dout * qf[i] * qf[i] + 2.f * pf[i] * r[i];
        }
    }
    __syncthreads();
#pragma unroll
    for (int i = 0; i < 8; i++) {
        atomicAdd(&Ss[cc + i], s[i]);
        atomicAdd(&Sq[cc + i], q[i]);
    }
    __syncthreads();
    if (t < (1 << logC)) {
        atomicAdd(&g_sum[t], (double)Ss[t]);
        atomicAdd(&g_sumsq[t], (double)Sq[t]);
    }
}

__global__ void k_finalize(const float* __restrict__ gn, int C, const float* __restrict__ comb) {
    int c = threadIdx.x;
    if (c < C) {
        double s = g_sum[c], q = g_sumsq[c];
        if (comb) {
            double bc = (double)comb[c];
            q += 2.0 * bc * s + (double)NE * bc * bc;
            s += (double)NE * bc;
        }
        float invE = 1.f / (float)NE;
        float m  = (float)(s * invE);
        float m2 = (float)(q * invE);
        float g = gn[c], b = gn[C + c], ms = gn[2 * C + c];
        float var = m2 - 2.f * ms * m * m + ms * ms * m * m;
        float rs = rsqrtf(var + EPSV);
        g_alpha[c] = g * rs;
        g_beta[c]  = b - g * rs * ms * m;
        g_sum[c] = 0.0;
        g_sumsq[c] = 0.0;
    }
}

// pre-permute weights into mma B-fragment layout
__global__ void k_trp(const float* __restrict__ Wa, const float* __restrict__ Wb,
                      uint32_t* __restrict__ out, int K, int N) {
    int tot = N * (K >> 1);
    int i = blockIdx.x * blockDim.x + threadIdx.x;
    for (; i < tot; i += gridDim.x * blockDim.x) {
        int n = i / (K >> 1);
        int kp = i - n * (K >> 1);
        int k = kp << 1;
        float v0 = Wa[(size_t)k * N + n], v1 = Wa[(size_t)(k + 1) * N + n];
        if (Wb) { v0 -= Wb[(size_t)k * N + n]; v1 -= Wb[(size_t)(k + 1) * N + n]; }
        int ch = k >> 5;
        int kpair = (k >> 1) & 15;
        int ksP = kpair >> 3, khi8 = (kpair >> 2) & 1, t4P = kpair & 3;
        int nblk = n >> 7, r = n & 127;
        int ni = r & 31, wn = r >> 5, nf = ni >> 3, gB = ni & 7;
        int slot = ((((wn << 1) + ksP) << 2) + nf) * 64 + (gB << 3) + (t4P << 1) + khi8;
        out[((size_t)nblk * (K >> 5) + ch) * 2048 + slot] = h2u(__floats2half2_rn(v0, v1));
    }
}

// ---------------- fp16 mma GEMM (generalized M-tile) ----------------
// Tile: rows = MW*32, cols = NB*128. Warps: warpM = w%MW, warpN = w/MW (NB*4 slices).
// THREADS = MW * NB * 128. Producer warps = MW*4 (stage A tile, 8 rows each).
// MODE 0: plain half A. MODE 1: relu(affine(A)). MODE 2: relu(affine(P[sdst]+Q[ssrc]+comb))
// STATS: per-channel sum/sumsq. PAIR: blockIdx.y selects (Bp,Co)/(Bp2,Co2).
template <int MODE, bool STATS, bool PAIR, int NB, int MW, int THREADS>
__global__ void __launch_bounds__(THREADS, 2)
wm_gemm(const __half* __restrict__ A, const __half* __restrict__ Qb,
        const uint32_t* __restrict__ Bp, const uint32_t* __restrict__ Bp2,
        const float* __restrict__ bias, const float* __restrict__ comb,
        __half* __restrict__ Co, __half* __restrict__ Co2,
        int M, int K) {
    __shared__ uint32_t sAu[2][MW * 512];
    __shared__ float Ssum[NB * 128], Ssq[NB * 128];
    const int N = NB * 128;
    const int ROWS = MW * 32;
    const int PRODW = MW * 4;
    const int tid = threadIdx.x;
    const int w = tid >> 5, lane = tid & 31;
    const int g = lane >> 2, t4 = lane & 3;
    const int warpM = w & (MW - 1), warpN = w / MW;
    const int nb = warpN >> 2, wn = warpN & 3;
    const int m0 = blockIdx.x * ROWS;
    const bool prod = (w < PRODW);
    const uint32_t* Bu = (PAIR && blockIdx.y) ? Bp2 : Bp;
    __half* Cu = (PAIR && blockIdx.y) ? Co2 : Co;

    if (STATS) {
#pragma unroll
        for (int i = tid; i < NB * 128; i += THREADS) { Ssum[i] = 0.f; Ssq[i] = 0.f; }
    }

    float c[2][4][4];
#pragma unroll
    for (int i = 0; i < 2; i++)
#pragma unroll
        for (int j = 0; j < 4; j++)
#pragma unroll
            for (int k = 0; k < 4; k++) c[i][j][k] = 0.f;

    const int rowlane = lane >> 2, kq8 = lane & 3;
    const int r = ((w & (PRODW - 1)) << 3) + rowlane;
    const int gm = m0 + r;
    const bool valid = prod && (gm < M);
    int rd = 0, rs = 0;
    if (MODE == 2) { rd = valid ? g_sdst[gm] : 0; rs = valid ? g_ssrc[gm] : 0; }
    int slotk[4];
    {
        const int wm = r >> 5, ri = r & 31, mf = ri >> 4, rb = ri & 15;
        const int gA = rb & 7, rowhi = rb >> 3;
        const int ksP = kq8 >> 1, khi8 = kq8 & 1;
#pragma unroll
        for (int i = 0; i < 4; i++)
            slotk[i] = ((((wm << 1) + ksP) << 1) + mf) * 128 + (gA << 4) + (i << 2) + rowhi + (khi8 << 1);
    }
    const int nch = K >> 5;

    auto load_regs = [&](int ch, uint32_t* hu) {
        const int cg = (ch << 5) + (kq8 << 3);
        if (!valid) { hu[0] = hu[1] = hu[2] = hu[3] = 0; return; }
        if (MODE == 0) {
            uint4 v = *(const uint4*)(A + (size_t)gm * K + cg);
            hu[0] = v.x; hu[1] = v.y; hu[2] = v.z; hu[3] = v.w;
            return;
        }
        float4 al0 = *(const float4*)(g_alpha + cg);
        float4 al1 = *(const float4*)(g_alpha + cg + 4);
        float4 be0 = *(const float4*)(g_beta + cg);
        float4 be1 = *(const float4*)(g_beta + cg + 4);
        if (MODE == 2) {
            float4 cb0 = *(const float4*)(comb + cg);
            float4 cb1 = *(const float4*)(comb + cg + 4);
            be0.x = fmaf(al0.x, cb0.x, be0.x); be0.y = fmaf(al0.y, cb0.y, be0.y);
            be0.z = fmaf(al0.z, cb0.z, be0.z); be0.w = fmaf(al0.w, cb0.w, be0.w);
            be1.x = fmaf(al1.x, cb1.x, be1.x); be1.y = fmaf(al1.y, cb1.y, be1.y);
            be1.z = fmaf(al1.z, cb1.z, be1.z); be1.w = fmaf(al1.w, cb1.w, be1.w);
        }
        if (MODE == 1) {
            uint4 v = *(const uint4*)(A + (size_t)gm * K + cg);
            hu[0] = aff2(v.x, al0.x, al0.y, be0.x, be0.y);
            hu[1] = aff2(v.y, al0.z, al0.w, be0.z, be0.w);
            hu[2] = aff2(v.z, al1.x, al1.y, be1.x, be1.y);
            hu[3] = aff2(v.w, al1.z, al1.w, be1.z, be1.w);
        } else {
            uint4 pv = *(const uint4*)(A + (size_t)rd * K + cg);
            uint4 qv = *(const uint4*)(Qb + (size_t)rs * K + cg);
            hu[0] = aff2s(pv.x, qv.x, al0.x, al0.y, be0.x, be0.y);
            hu[1] = aff2s(pv.y, qv.y, al0.z, al0.w, be0.z, be0.w);
            hu[2] = aff2s(pv.z, qv.z, al1.x, al1.y, be1.x, be1.y);
            hu[3] = aff2s(pv.w, qv.w, al1.z, al1.w, be1.z, be1.w);
        }
    };

    if (prod) {
        uint32_t hu[4];
        load_regs(0, hu);
#pragma unroll
        for (int j = 0; j < 4; j++) sAu[0][slotk[j]] = hu[j];
    }
    __syncthreads();

    for (int ch = 0; ch < nch; ch++) {
        uint32_t hn[4];
        if (prod && ch + 1 < nch) load_regs(ch + 1, hn);

        const uint4* A4 = (const uint4*)sAu[ch & 1];
        const uint2* B2 = (const uint2*)(Bu + ((size_t)nb * nch + ch) * 2048);
#pragma unroll
        for (int ks = 0; ks < 2; ks++) {
            uint4 af[2];
#pragma unroll
            for (int mf = 0; mf < 2; mf++)
                af[mf] = A4[((((warpM << 1) + ks) << 1) + mf) * 32 + lane];
            uint2 bf[4];
#pragma unroll
            for (int nf = 0; nf < 4; nf++)
                bf[nf] = B2[((((wn << 1) + ks) << 2) + nf) * 32 + lane];
#pragma unroll
            for (int mf = 0; mf < 2; mf++)
#pragma unroll
                for (int nf = 0; nf < 4; nf++) {
                    asm volatile(
                        "mma.sync.aligned.m16n8k16.row.col.f32.f16.f16.f32 "
                        "{%0,%1,%2,%3}, {%4,%5,%6,%7}, {%8,%9}, {%0,%1,%2,%3};"
                        : "+f"(c[mf][nf][0]), "+f"(c[mf][nf][1]),
                          "+f"(c[mf][nf][2]), "+f"(c[mf][nf][3])
                        : "r"(af[mf].x), "r"(af[mf].y), "r"(af[mf].z), "r"(af[mf].w),
                          "r"(bf[nf].x), "r"(bf[nf].y));
                }
        }
        if (prod && ch + 1 < nch) {
#pragma unroll
            for (int j = 0; j < 4; j++) sAu[(ch + 1) & 1][slotk[j]] = hn[j];
        }
        __syncthreads();
    }

#pragma unroll
    for (int mf = 0; mf < 2; mf++) {
        int r0 = m0 + warpM * 32 + mf * 16 + g;
#pragma unroll
        for (int nf = 0; nf < 4; nf++) {
            int colL = nb * 128 + wn * 32 + nf * 8 + 2 * t4;
            float b0 = bias ? bias[colL] : 0.f;
            float b1 = bias ? bias[colL + 1] : 0.f;
            float v0 = c[mf][nf][0] + b0, v1 = c[mf][nf][1] + b1;
            float v2 = c[mf][nf][2] + b0, v3 = c[mf][nf][3] + b1;
            if (r0 < M)
                *(__half2*)(Cu + (size_t)r0 * N + colL) = __floats2half2_rn(v0, v1);
            if (r0 + 8 < M)
                *(__half2*)(Cu + (size_t)(r0 + 8) * N + colL) = __floats2half2_rn(v2, v3);
            if (STATS) {
                atomicAdd(&Ssum[colL], v0 + v2);
                atomicAdd(&Ssum[colL + 1], v1 + v3);
                atomicAdd(&Ssq[colL], fmaf(v0, v0, v2 * v2));
                atomicAdd(&Ssq[colL + 1], fmaf(v1, v1, v3 * v3));
            }
        }
    }
    if (STATS) {
        __syncthreads();
#pragma unroll
        for (int i = tid; i < NB * 128; i += THREADS) {
            atomicAdd(&g_sum[i], (double)Ssum[i]);
            atomicAdd(&g_sumsq[i], (double)Ssq[i]);
        }
    }
}

// ---------------- segment-reduce aggregations (8 ch/thread) ----------------
__global__ void k_agg_seg(const __half* __restrict__ H, __half* __restrict__ node, int logC) {
    const int sh = logC - 3;
    size_t tot = (size_t)NN << sh;
    for (size_t idx = (size_t)blockIdx.x * blockDim.x + threadIdx.x; idx < tot;
         idx += (size_t)gridDim.x * blockDim.x) {
        int n = (int)(idx >> sh);
        int cc = ((int)idx & ((1 << sh) - 1)) << 3;
        float4 al0 = *(const float4*)(g_alpha + cc);
        float4 al1 = *(const float4*)(g_alpha + cc + 4);
        float4 be0 = *(const float4*)(g_beta + cc);
        float4 be1 = *(const float4*)(g_beta + cc + 4);
        int p0 = g_seg[n], p1 = g_seg[n + 1];
        float s[8];
#pragma unroll
        for (int i = 0; i < 8; i++) s[i] = 0.f;
        for (int p = p0; p < p1; p++) {
            uint4 hv = *(const uint4*)(H + ((size_t)p << logC) + cc);
            float2 a;
            a = uf2(hv.x);
            s[0] += fmaxf(fmaf(al0.x, a.x, be0.x), 0.f);
            s[1] += fmaxf(fmaf(al0.y, a.y, be0.y), 0.f);
            a = uf2(hv.y);
            s[2] += fmaxf(fmaf(al0.z, a.x, be0.z), 0.f);
            s[3] += fmaxf(fmaf(al0.w, a.y, be0.w), 0.f);
            a = uf2(hv.z);
            s[4] += fmaxf(fmaf(al1.x, a.x, be1.x), 0.f);
            s[5] += fmaxf(fmaf(al1.y, a.y, be1.y), 0.f);
            a = uf2(hv.w);
            s[6] += fmaxf(fmaf(al1.z, a.x, be1.z), 0.f);
            s[7] += fmaxf(fmaf(al1.w, a.y, be1.w), 0.f);
        }
        float inv = g_invdeg[n];
        uint4 o;
        o.x = h2u(__floats2half2_rn(s[0] * inv, s[1] * inv));
        o.y = h2u(__floats2half2_rn(s[2] * inv, s[3] * inv));
        o.z = h2u(__floats2half2_rn(s[4] * inv, s[5] * inv));
        o.w = h2u(__floats2half2_rn(s[6] * inv, s[7] * inv));
        *(uint4*)(node + ((size_t)n << logC) + cc) = o;
    }
}

__global__ void k_agg_pq_seg(const __half* __restrict__ P, const __half* __restrict__ Qb,
                             const float* __restrict__ comb, __half* __restrict__ node) {
    size_t tot = (size_t)NN * 32;
    for (size_t idx = (size_t)blockIdx.x * blockDim.x + threadIdx.x; idx < tot;
         idx += (size_t)gridDim.x * blockDim.x) {
        int n = (int)(idx >> 5);
        int cc = ((int)idx & 31) << 3;
        float4 al0 = *(const float4*)(g_alpha + cc);
        float4 al1 = *(const float4*)(g_alpha + cc + 4);
        float4 be0 = *(const float4*)(g_beta + cc);
        float4 be1 = *(const float4*)(g_beta + cc + 4);
        float4 cb0 = *(const float4*)(comb + cc);
        float4 cb1 = *(const float4*)(comb + cc + 4);
        uint4 pv = *(const uint4*)(P + ((size_t)n << 8) + cc);
        float pb[8];
        {
            float2 a;
            a = uf2(pv.x); pb[0] = a.x + cb0.x; pb[1] = a.y + cb0.y;
            a = uf2(pv.y); pb[2] = a.x + cb0.z; pb[3] = a.y + cb0.w;
            a = uf2(pv.z); pb[4] = a.x + cb1.x; pb[5] = a.y + cb1.y;
            a = uf2(pv.w); pb[6] = a.x + cb1.z; pb[7] = a.y + cb1.w;
        }
        int p0 = g_seg[n], p1 = g_seg[n + 1];
        float s[8];
#pragma unroll
        for (int i = 0; i < 8; i++) s[i] = 0.f;
        for (int p = p0; p < p1; p++) {
            int sidx = g_ssrc[p];
            uint4 qv = *(const uint4*)(Qb + ((size_t)sidx << 8) + cc);
            float2 a;
            a = uf2(qv.x);
            s[0] += fmaxf(fmaf(al0.x, pb[0] + a.x, be0.x), 0.f);
            s[1] += fmaxf(fmaf(al0.y, pb[1] + a.y, be0.y), 0.f);
            a = uf2(qv.y);
            s[2] += fmaxf(fmaf(al0.z, pb[2] + a.x, be0.z), 0.f);
            s[3] += fmaxf(fmaf(al0.w, pb[3] + a.y, be0.w), 0.f);
            a = uf2(qv.z);
            s[4] += fmaxf(fmaf(al1.x, pb[4] + a.x, be1.x), 0.f);
            s[5] += fmaxf(fmaf(al1.y, pb[5] + a.y, be1.y), 0.f);
            a = uf2(qv.w);
            s[6] += fmaxf(fmaf(al1.z, pb[6] + a.x, be1.z), 0.f);
            s[7] += fmaxf(fmaf(al1.w, pb[7] + a.y, be1.w), 0.f);
        }
        float inv = g_invdeg[n];
        uint4 o;
        o.x = h2u(__floats2half2_rn(s[0] * inv, s[1] * inv));
        o.y = h2u(__floats2half2_rn(s[2] * inv, s[3] * inv));
        o.z = h2u(__floats2half2_rn(s[4] * inv, s[5] * inv));
        o.w = h2u(__floats2half2_rn(s[6] * inv, s[7] * inv));
        *(uint4*)(node + ((size_t)n << 8) + cc) = o;
    }
}

__global__ void k_pool_seg(const __half* __restrict__ h3) {
    int gph = blockIdx.x, t = threadIdx.x;
    int n0 = g_gseg[gph], n1 = g_gseg[gph + 1];
    float s = 0.f;
    for (int n = n0; n < n1; n++) s += __half2float(h3[(size_t)n * 256 + t]);
    g_pool[gph * 256 + t] = s / fmaxf((float)(n1 - n0), 1.f);
}

__global__ void k_head(const float* __restrict__ W1, const float* __restrict__ b1,
                       const float* __restrict__ W2, const float* __restrict__ b2,
                       float* __restrict__ out) {
    __shared__ float gv[256], hid[256], r0[256], r1[256];
    int r = blockIdx.x, t = threadIdx.x;
    gv[t] = g_pool[r * 256 + t];
    __syncthreads();
    float a = b1[t];
    for (int k = 0; k < 256; k++) a = fmaf(gv[k], W1[k * 256 + t], a);
    hid[t] = fmaxf(a, 0.f);
    __syncthreads();
    r0[t] = hid[t] * W2[t * 2 + 0];
    r1[t] = hid[t] * W2[t * 2 + 1];
    __syncthreads();
    for (int s = 128; s > 0; s >>= 1) {
        if (t < s) { r0[t] += r0[t + s]; r1[t] += r1[t + s]; }
        __syncthreads();
    }
    if (t == 0) {
        out[r * 2 + 0] = r0[0] + b2[0];
        out[r * 2 + 1] = r1[0] + b2[1];
    }
}

// ---------------- launcher ----------------
extern "C" void kernel_launch(void* const* d_in, const int* in_sizes, int n_in,
                              void* d_out, int out_size) {
    const float* x      = (const float*)d_in[0];
    const void*  ei     = d_in[1];
    const void*  bt     = d_in[2];
    const float* c1_w1  = (const float*)d_in[3];
    const float* c1_b1  = (const float*)d_in[4];
    const float* c1_gn1 = (const float*)d_in[5];
    const float* c1_w2  = (const float*)d_in[6];
    const float* c1_b2  = (const float*)d_in[7];
    const float* c1_gn2 = (const float*)d_in[8];
    const float* c1_w3  = (const float*)d_in[9];
    const float* c1_b3  = (const float*)d_in[10];
    const float* c1_gn3 = (const float*)d_in[11];
    const float* c2_w1  = (const float*)d_in[12];
    const float* c2_b1  = (const float*)d_in[13];
    const float* c2_gn1 = (const float*)d_in[14];
    const float* c2_w2  = (const float*)d_in[15];
    const float* c2_b2  = (const float*)d_in[16];
    const float* c2_gn2 = (const float*)d_in[17];
    const float* c3_w1  = (const float*)d_in[18];
    const float* c3_b1  = (const float*)d_in[19];
    const float* c3_gn1 = (const float*)d_in[20];
    const float* lw1    = (const float*)d_in[21];
    const float* lb1    = (const float*)d_in[22];
    const float* lw2    = (const float*)d_in[23];
    const float* lb2    = (const float*)d_in[24];
    float* out = (float*)d_out;
    (void)in_sizes; (void)n_in; (void)out_size;

    __half *pP, *pQ, *ph1, *ph2, *ph3, *pe0, *pe1;
    uint32_t *pwt, *pwtA, *pwtB;
    int *phist, *pdout, *pghist;
    cudaGetSymbolAddress((void**)&pP, g_P);
    cudaGetSymbolAddress((void**)&pQ, g_Q);
    cudaGetSymbolAddress((void**)&ph1, g_h1);
    cudaGetSymbolAddress((void**)&ph2, g_h2);
    cudaGetSymbolAddress((void**)&ph3, g_h3);
    cudaGetSymbolAddress((void**)&pe0, g_e0);
    cudaGetSymbolAddress((void**)&pe1, g_e1);
    cudaGetSymbolAddress((void**)&pwt, g_wtp);
    cudaGetSymbolAddress((void**)&pwtA, g_wtpA);
    cudaGetSymbolAddress((void**)&pwtB, g_wtpB);
    cudaGetSymbolAddress((void**)&phist, g_hist);
    cudaGetSymbolAddress((void**)&pdout, g_dout);
    cudaGetSymbolAddress((void**)&pghist, g_ghist);

    // setup
    cudaMemsetAsync(phist, 0, NN * sizeof(int));
    cudaMemsetAsync(pdout, 0, NN * sizeof(int));
    cudaMemsetAsync(pghist, 0, NG * sizeof(int));
    k_convert<<<1024, 256>>>(ei, bt);
    k_scan_nodes<<<1, 1024>>>();
    k_scan_graphs<<<1, 1024>>>();
    k_scatter<<<1024, 256>>>();

    const int ET128 = NE / 128;          // 128-row edge tiles (block 1)
    const int ET = NE / 64;              // 64-row edge tiles (block 2)
    const int NT = (NN + 63) / 64;

    // block 1 (C=128, 3 layers) — MW=4, 512 threads
    k_l1<<<2048, 128>>>(x, c1_w1);
    k_stats2<<<2048, 256>>>(pP, pQ, 7);
    k_finalize<<<1, 256>>>(c1_gn1, 128, c1_b1);
    k_trp<<<64, 256>>>(c1_w2, nullptr, pwt, 128, 128);
    wm_gemm<2, true, false, 1, 4, 512><<<ET128, 512>>>(pP, pQ, pwt, nullptr, c1_b2, c1_b1, pe0, nullptr, NE, 128);
    k_finalize<<<1, 256>>>(c1_gn2, 128, nullptr);
    k_trp<<<64, 256>>>(c1_w3, nullptr, pwtA, 128, 128);
    wm_gemm<1, true, false, 1, 4, 512><<<ET128, 512>>>(pe0, nullptr, pwtA, nullptr, c1_b3, nullptr, pe1, nullptr, NE, 128);
    k_finalize<<<1, 256>>>(c1_gn3, 128, nullptr);
    k_agg_seg<<<4096, 256>>>(pe1, ph1, 7);

    // block 2 (C=256, 2 layers) — NB=2, MW=2, 512 threads
    k_trp<<<128, 256>>>(c2_w1, c2_w1 + 128 * 256, pwtA, 128, 256);
    k_trp<<<128, 256>>>(c2_w1 + 128 * 256, nullptr, pwtB, 128, 256);
    wm_gemm<0, false, true, 2, 2, 512><<<dim3(NT, 2), 512>>>(ph1, nullptr, pwtA, pwtB, nullptr, nullptr, pP, pQ, NN, 128);
    k_stats2<<<2048, 256>>>(pP, pQ, 8);
    k_finalize<<<1, 256>>>(c2_gn1, 256, c2_b1);
    k_trp<<<256, 256>>>(c2_w2, nullptr, pwt, 256, 256);
    wm_gemm<2, true, false, 2, 2, 512><<<ET, 512>>>(pP, pQ, pwt, nullptr, c2_b2, c2_b1, pe0, nullptr, NE, 256);
    k_finalize<<<1, 256>>>(c2_gn2, 256, nullptr);
    k_agg_seg<<<8192, 256>>>(pe0, ph2, 8);

    // block 3 (C=256, 1 layer — no edge GEMM)
    k_trp<<<256, 256>>>(c3_w1, c3_w1 + 256 * 256, pwtA, 256, 256);
    k_trp<<<256, 256>>>(c3_w1 + 256 * 256, nullptr, pwtB, 256, 256);
    wm_gemm<0, false, true, 2, 2, 512><<<dim3(NT, 2), 512>>>(ph2, nullptr, pwtA, pwtB, nullptr, nullptr, pP, pQ, NN, 256);
    k_stats2<<<2048, 256>>>(pP, pQ, 8);
    k_finalize<<<1, 256>>>(c3_gn1, 256, c3_b1);
    k_agg_pq_seg<<<4096, 256>>>(pP, pQ, c3_b1, ph3);

    // pool + head
    k_pool_seg<<<NG, 256>>>(ph3);
    k_head<<<NG, 256>>>(lw1, lb1, lw2, lb2, out);
}

// round 16
// speedup vs baseline: 1.4969x; 1.0013x over previous
#include <cuda_runtime.h>
#include <cuda_fp16.h>
#include <cstdint>

#define NN 100000
#define NE 400000
#define NG 1000
#define EPSV 1e-5f

__device__ __half g_P[(size_t)NN * 256];
__device__ __half g_Q[(size_t)NN * 256];
__device__ __half g_h1[(size_t)NN * 128];
__device__ __half g_h2[(size_t)NN * 256];
__device__ __half g_h3[(size_t)NN * 256];
__device__ __half g_e0[(size_t)NE * 256];
__device__ __half g_e1[(size_t)NE * 128];
__device__ int    g_src[NE];
__device__ int    g_dst[NE];
__device__ int    g_ssrc[NE];
__device__ int    g_sdst[NE];
__device__ int    g_batch[NN];
__device__ int    g_hist[NN];
__device__ int    g_dout[NN];
__device__ int    g_seg[NN + 1];
__device__ int    g_cur[NN];
__device__ int    g_ghist[NG];
__device__ int    g_gseg[NG + 1];
__device__ float  g_invdeg[NN];
__device__ double g_sum[256];
__device__ double g_sumsq[256];
__device__ float  g_alpha[256];
__device__ float  g_beta[256];
__device__ uint32_t g_wtp [2 * 8 * 2048];
__device__ uint32_t g_wtpA[2 * 8 * 2048];
__device__ uint32_t g_wtpB[2 * 8 * 2048];
__device__ float  g_pool[NG * 256];

__device__ __forceinline__ uint32_t h2u(__half2 h) { return *reinterpret_cast<uint32_t*>(&h); }
__device__ __forceinline__ __half2 u2h(uint32_t u) { return *reinterpret_cast<__half2*>(&u); }
__device__ __forceinline__ float2 uf2(uint32_t u) { return __half22float2(u2h(u)); }

__device__ __forceinline__ uint32_t aff2(uint32_t u, float ax, float ay, float bx, float by) {
    float2 f = uf2(u);
    return h2u(__floats2half2_rn(fmaxf(fmaf(ax, f.x, bx), 0.f),
                                 fmaxf(fmaf(ay, f.y, by), 0.f)));
}
__device__ __forceinline__ uint32_t aff2s(uint32_t up, uint32_t uq,
                                          float ax, float ay, float bx, float by) {
    float2 p = uf2(up), q = uf2(uq);
    return h2u(__floats2half2_rn(fmaxf(fmaf(ax, p.x + q.x, bx), 0.f),
                                 fmaxf(fmaf(ay, p.y + q.y, by), 0.f)));
}

// ---------------- convert + histograms ----------------
__global__ void k_convert(const void* __restrict__ ei, const void* __restrict__ bt) {
    __shared__ int s64;
    if (threadIdx.x == 0) {
        const unsigned long long* e = (const unsigned long long*)ei;
        int f = 1;
        for (int i = 0; i < 256; i++)
            if (e[i] >= (unsigned long long)NN) { f = 0; break; }
        s64 = f;
    }
    __syncthreads();
    const int is64 = s64;
    int i0 = blockIdx.x * blockDim.x + threadIdx.x;
    int st = gridDim.x * blockDim.x;
    for (int k = i0; k < NE; k += st) {
        int s, d;
        if (is64) {
            const long long* e = (const long long*)ei;
            s = (int)e[k]; d = (int)e[NE + k];
        } else {
            const int* e = (const int*)ei;
            s = e[k]; d = e[NE + k];
        }
        g_src[k] = s; g_dst[k] = d;
        atomicAdd(&g_hist[d], 1);
        atomicAdd(&g_dout[s], 1);
    }
    for (int k = i0; k < NN; k += st) {
        int b = is64 ? (int)((const long long*)bt)[k] : ((const int*)bt)[k];
        g_batch[k] = b;
        atomicAdd(&g_ghist[b], 1);
    }
}

__global__ void k_scan_nodes() {
    __shared__ int wsum[32];
    __shared__ int carry;
    int t = threadIdx.x, lane = t & 31, wid = t >> 5;
    if (t == 0) carry = 0;
    __syncthreads();
    for (int base = 0; base < NN; base += 1024) {
        int i = base + t;
        int v = (i < NN) ? g_hist[i] : 0;
        int x = v;
#pragma unroll
        for (int off = 1; off < 32; off <<= 1) {
            int y = __shfl_up_sync(0xFFFFFFFFu, x, off);
            if (lane >= off) x += y;
        }
        if (lane == 31) wsum[wid] = x;
        __syncthreads();
        if (wid == 0) {
            int wv = wsum[lane];
#pragma unroll
            for (int off = 1; off < 32; off <<= 1) {
                int y = __shfl_up_sync(0xFFFFFFFFu, wv, off);
                if (lane >= off) wv += y;
            }
            wsum[lane] = wv;
        }
        __syncthreads();
        int incl = x + (wid ? wsum[wid - 1] : 0);
        int c = carry;
        if (i < NN) {
            g_seg[i] = c + incl - v;
            g_cur[i] = c + incl - v;
            g_invdeg[i] = 1.f / fmaxf((float)v, 1.f);
        }
        __syncthreads();
        if (t == 1023) carry += incl;
        __syncthreads();
    }
    if (t == 0) g_seg[NN] = carry;
}

__global__ void k_scan_graphs() {
    __shared__ int sb[1024];
    int t = threadIdx.x;
    int v = (t < NG) ? g_ghist[t] : 0;
    sb[t] = v;
    __syncthreads();
    for (int off = 1; off < 1024; off <<= 1) {
        int x = sb[t];
        int y = (t >= off) ? sb[t - off] : 0;
        __syncthreads();
        sb[t] = x + y;
        __syncthreads();
    }
    if (t < NG) g_gseg[t] = sb[t] - v;
    if (t == 1023) g_gseg[NG] = sb[1023];
}

__global__ void k_scatter() {
    int i = blockIdx.x * blockDim.x + threadIdx.x;
    for (; i < NE; i += gridDim.x * blockDim.x) {
        int d = g_dst[i];
        int p = atomicAdd(&g_cur[d], 1);
        g_ssrc[p] = g_src[i];
        g_sdst[p] = d;
    }
}

// layer-1 of block 1
__global__ void k_l1(const float* __restrict__ x, const float* __restrict__ W) {
    __shared__ float wd[5 * 128], wb[5 * 128];
    int c = threadIdx.x;
#pragma unroll
    for (int k = 0; k < 5; k++) {
        float t = W[(5 + k) * 128 + c];
        wb[k * 128 + c] = t;
        wd[k * 128 + c] = W[k * 128 + c] - t;
    }
    __syncthreads();
    for (int n = blockIdx.x; n < NN; n += gridDim.x) {
        float xv[5];
#pragma unroll
        for (int k = 0; k < 5; k++) xv[k] = x[n * 5 + k];
        float p = 0.f, q = 0.f;
#pragma unroll
        for (int k = 0; k < 5; k++) {
            p = fmaf(xv[k], wd[k * 128 + c], p);
            q = fmaf(xv[k], wb[k * 128 + c], q);
        }
        g_P[(size_t)n * 128 + c] = __float2half_rn(p);
        g_Q[(size_t)n * 128 + c] = __float2half_rn(q);
    }
}

// ---- factorized edge stats, 8 channels/thread (uint4 gathers) ----
__global__ void k_stats2(const __half* __restrict__ P, const __half* __restrict__ Qb, int logC) {
    __shared__ float Ss[256], Sq[256];
    const int opn = 1 << (logC - 3);
    const int t = threadIdx.x;
    const int nlane = t >> (logC - 3);
    const int npb = 256 >> (logC - 3);
    const int cc = (t & (opn - 1)) << 3;
    if (t < (1 << logC)) { Ss[t] = 0.f; Sq[t] = 0.f; }

    float s[8], q[8];
#pragma unroll
    for (int i = 0; i < 8; i++) { s[i] = 0.f; q[i] = 0.f; }

    const int ngroups = (NN + npb - 1) / npb;
    for (int ng = blockIdx.x; ng < ngroups; ng += gridDim.x) {
        int n = ng * npb + nlane;
        if (n >= NN) continue;
        int p0 = g_seg[n], p1 = g_seg[n + 1];
        float din = (float)(p1 - p0);
        float dout = (float)g_dout[n];
        uint4 pv = *(const uint4*)(P + ((size_t)n << logC) + cc);
        uint4 qv = *(const uint4*)(Qb + ((size_t)n << logC) + cc);
        float pf[8], qf[8];
        {
            float2 a;
            a = uf2(pv.x); pf[0] = a.x; pf[1] = a.y;
            a = uf2(pv.y); pf[2] = a.x; pf[3] = a.y;
            a = uf2(pv.z); pf[4] = a.x; pf[5] = a.y;
            a = uf2(pv.w); pf[6] = a.x; pf[7] = a.y;
            a = uf2(qv.x); qf[0] = a.x; qf[1] = a.y;
            a = uf2(qv.y); qf[2] = a.x; qf[3] = a.y;
            a = uf2(qv.z); qf[4] = a.x; qf[5] = a.y;
            a = uf2(qv.w); qf[6] = a.x; qf[7] = a.y;
        }
        float r[8];
#pragma unroll
        for (int i = 0; i < 8; i++) r[i] = 0.f;
        for (int p = p0; p < p1; p++) {
            int sidx = g_ssrc[p];
            uint4 sv = *(const uint4*)(Qb + ((size_t)sidx << logC) + cc);
            float2 a;
            a = uf2(sv.x); r[0] += a.x; r[1] += a.y;
            a = uf2(sv.y); r[2] += a.x; r[3] += a.y;
            a = uf2(sv.z); r[4] += a.x; r[5] += a.y;
            a = uf2(sv.w); r[6] += a.x; r[7] += a.y;
        }
#pragma unroll
        for (int i = 0; i < 8; i++) {
            s[i] += din * pf[i] + dout * qf[i];
            q[i] += din * pf[i] * pf[i] + dout * qf[i] * qf[i] + 2.f * pf[i] * r[i];
        }
    }
    __syncthreads();
#pragma unroll
    for (int i = 0; i < 8; i++) {
        atomicAdd(&Ss[cc + i], s[i]);
        atomicAdd(&Sq[cc + i], q[i]);
    }
    __syncthreads();
    if (t < (1 << logC)) {
        atomicAdd(&g_sum[t], (double)Ss[t]);
        atomicAdd(&g_sumsq[t], (double)Sq[t]);
    }
}

__global__ void k_finalize(const float* __restrict__ gn, int C, const float* __restrict__ comb) {
    int c = threadIdx.x;
    if (c < C) {
        double s = g_sum[c], q = g_sumsq[c];
        if (comb) {
            double bc = (double)comb[c];
            q += 2.0 * bc * s + (double)NE * bc * bc;
            s += (double)NE * bc;
        }
        float invE = 1.f / (float)NE;
        float m  = (float)(s * invE);
        float m2 = (float)(q * invE);
        float g = gn[c], b = gn[C + c], ms = gn[2 * C + c];
        float var = m2 - 2.f * ms * m * m + ms * ms * m * m;
        float rs = rsqrtf(var + EPSV);
        g_alpha[c] = g * rs;
        g_beta[c]  = b - g * rs * ms * m;
        g_sum[c] = 0.0;
        g_sumsq[c] = 0.0;
    }
}

// pre-permute weights into mma B-fragment layout
__global__ void k_trp(const float* __restrict__ Wa, const float* __restrict__ Wb,
                      uint32_t* __restrict__ out, int K, int N) {
    int tot = N * (K >> 1);
    int i = blockIdx.x * blockDim.x + threadIdx.x;
    for (; i < tot; i += gridDim.x * blockDim.x) {
        int n = i / (K >> 1);
        int kp = i - n * (K >> 1);
        int k = kp << 1;
        float v0 = Wa[(size_t)k * N + n], v1 = Wa[(size_t)(k + 1) * N + n];
        if (Wb) { v0 -= Wb[(size_t)k * N + n]; v1 -= Wb[(size_t)(k + 1) * N + n]; }
        int ch = k >> 5;
        int kpair = (k >> 1) & 15;
        int ksP = kpair >> 3, khi8 = (kpair >> 2) & 1, t4P = kpair & 3;
        int nblk = n >> 7, r = n & 127;
        int ni = r & 31, wn = r >> 5, nf = ni >> 3, gB = ni & 7;
        int slot = ((((wn << 1) + ksP) << 2) + nf) * 64 + (gB << 3) + (t4P << 1) + khi8;
        out[((size_t)nblk * (K >> 5) + ch) * 2048 + slot] = h2u(__floats2half2_rn(v0, v1));
    }
}

// ---------------- fp16 mma GEMM (generalized M-tile) ----------------
// Tile: rows = MW*32, cols = NB*128. Warps: warpM = w%MW, warpN = w/MW (NB*4 slices).
// THREADS = MW * NB * 128. Producer warps = MW*4 (stage A tile, 8 rows each).
// MODE 0: plain half A. MODE 1: relu(affine(A)). MODE 2: relu(affine(P[sdst]+Q[ssrc]+comb))
// STATS: per-channel sum/sumsq. PAIR: blockIdx.y selects (Bp,Co)/(Bp2,Co2).
template <int MODE, bool STATS, bool PAIR, int NB, int MW, int THREADS>
__global__ void __launch_bounds__(THREADS, 2)
wm_gemm(const __half* __restrict__ A, const __half* __restrict__ Qb,
        const uint32_t* __restrict__ Bp, const uint32_t* __restrict__ Bp2,
        const float* __restrict__ bias, const float* __restrict__ comb,
        __half* __restrict__ Co, __half* __restrict__ Co2,
        int M, int K) {
    __shared__ uint32_t sAu[2][MW * 512];
    __shared__ float Ssum[NB * 128], Ssq[NB * 128];
    const int N = NB * 128;
    const int ROWS = MW * 32;
    const int PRODW = MW * 4;
    const int tid = threadIdx.x;
    const int w = tid >> 5, lane = tid & 31;
    const int g = lane >> 2, t4 = lane & 3;
    const int warpM = w & (MW - 1), warpN = w / MW;
    const int nb = warpN >> 2, wn = warpN & 3;
    const int m0 = blockIdx.x * ROWS;
    const bool prod = (w < PRODW);
    const uint32_t* Bu = (PAIR && blockIdx.y) ? Bp2 : Bp;
    __half* Cu = (PAIR && blockIdx.y) ? Co2 : Co;

    if (STATS) {
#pragma unroll
        for (int i = tid; i < NB * 128; i += THREADS) { Ssum[i] = 0.f; Ssq[i] = 0.f; }
    }

    float c[2][4][4];
#pragma unroll
    for (int i = 0; i < 2; i++)
#pragma unroll
        for (int j = 0; j < 4; j++)
#pragma unroll
            for (int k = 0; k < 4; k++) c[i][j][k] = 0.f;

    const int rowlane = lane >> 2, kq8 = lane & 3;
    const int r = ((w & (PRODW - 1)) << 3) + rowlane;
    const int gm = m0 + r;
    const bool valid = prod && (gm < M);
    int rd = 0, rs = 0;
    if (MODE == 2) { rd = valid ? g_sdst[gm] : 0; rs = valid ? g_ssrc[gm] : 0; }
    int slotk[4];
    {
        const int wm = r >> 5, ri = r & 31, mf = ri >> 4, rb = ri & 15;
        const int gA = rb & 7, rowhi = rb >> 3;
        const int ksP = kq8 >> 1, khi8 = kq8 & 1;
#pragma unroll
        for (int i = 0; i < 4; i++)
            slotk[i] = ((((wm << 1) + ksP) << 1) + mf) * 128 + (gA << 4) + (i << 2) + rowhi + (khi8 << 1);
    }
    const int nch = K >> 5;

    auto load_regs = [&](int ch, uint32_t* hu) {
        const int cg = (ch << 5) + (kq8 << 3);
        if (!valid) { hu[0] = hu[1] = hu[2] = hu[3] = 0; return; }
        if (MODE == 0) {
            uint4 v = *(const uint4*)(A + (size_t)gm * K + cg);
            hu[0] = v.x; hu[1] = v.y; hu[2] = v.z; hu[3] = v.w;
            return;
        }
        float4 al0 = *(const float4*)(g_alpha + cg);
        float4 al1 = *(const float4*)(g_alpha + cg + 4);
        float4 be0 = *(const float4*)(g_beta + cg);
        float4 be1 = *(const float4*)(g_beta + cg + 4);
        if (MODE == 2) {
            float4 cb0 = *(const float4*)(comb + cg);
            float4 cb1 = *(const float4*)(comb + cg + 4);
            be0.x = fmaf(al0.x, cb0.x, be0.x); be0.y = fmaf(al0.y, cb0.y, be0.y);
            be0.z = fmaf(al0.z, cb0.z, be0.z); be0.w = fmaf(al0.w, cb0.w, be0.w);
            be1.x = fmaf(al1.x, cb1.x, be1.x); be1.y = fmaf(al1.y, cb1.y, be1.y);
            be1.z = fmaf(al1.z, cb1.z, be1.z); be1.w = fmaf(al1.w, cb1.w, be1.w);
        }
        if (MODE == 1) {
            uint4 v = *(const uint4*)(A + (size_t)gm * K + cg);
            hu[0] = aff2(v.x, al0.x, al0.y, be0.x, be0.y);
            hu[1] = aff2(v.y, al0.z, al0.w, be0.z, be0.w);
            hu[2] = aff2(v.z, al1.x, al1.y, be1.x, be1.y);
            hu[3] = aff2(v.w, al1.z, al1.w, be1.z, be1.w);
        } else {
            uint4 pv = *(const uint4*)(A + (size_t)rd * K + cg);
            uint4 qv = *(const uint4*)(Qb + (size_t)rs * K + cg);
            hu[0] = aff2s(pv.x, qv.x, al0.x, al0.y, be0.x, be0.y);
            hu[1] = aff2s(pv.y, qv.y, al0.z, al0.w, be0.z, be0.w);
            hu[2] = aff2s(pv.z, qv.z, al1.x, al1.y, be1.x, be1.y);
            hu[3] = aff2s(pv.w, qv.w, al1.z, al1.w, be1.z, be1.w);
        }
    };

    if (prod) {
        uint32_t hu[4];
        load_regs(0, hu);
#pragma unroll
        for (int j = 0; j < 4; j++) sAu[0][slotk[j]] = hu[j];
    }
    __syncthreads();

    for (int ch = 0; ch < nch; ch++) {
        uint32_t hn[4];
        if (prod && ch + 1 < nch) load_regs(ch + 1, hn);

        const uint4* A4 = (const uint4*)sAu[ch & 1];
        const uint2* B2 = (const uint2*)(Bu + ((size_t)nb * nch + ch) * 2048);
#pragma unroll
        for (int ks = 0; ks < 2; ks++) {
            uint4 af[2];
#pragma unroll
            for (int mf = 0; mf < 2; mf++)
                af[mf] = A4[((((warpM << 1) + ks) << 1) + mf) * 32 + lane];
            uint2 bf[4];
#pragma unroll
            for (int nf = 0; nf < 4; nf++)
                bf[nf] = B2[((((wn << 1) + ks) << 2) + nf) * 32 + lane];
#pragma unroll
            for (int mf = 0; mf < 2; mf++)
#pragma unroll
                for (int nf = 0; nf < 4; nf++) {
                    asm volatile(
                        "mma.sync.aligned.m16n8k16.row.col.f32.f16.f16.f32 "
                        "{%0,%1,%2,%3}, {%4,%5,%6,%7}, {%8,%9}, {%0,%1,%2,%3};"
                        : "+f"(c[mf][nf][0]), "+f"(c[mf][nf][1]),
                          "+f"(c[mf][nf][2]), "+f"(c[mf][nf][3])
                        : "r"(af[mf].x), "r"(af[mf].y), "r"(af[mf].z), "r"(af[mf].w),
                          "r"(bf[nf].x), "r"(bf[nf].y));
                }
        }
        if (prod && ch + 1 < nch) {
#pragma unroll
            for (int j = 0; j < 4; j++) sAu[(ch + 1) & 1][slotk[j]] = hn[j];
        }
        __syncthreads();
    }

#pragma unroll
    for (int mf = 0; mf < 2; mf++) {
        int r0 = m0 + warpM * 32 + mf * 16 + g;
#pragma unroll
        for (int nf = 0; nf < 4; nf++) {
            int colL = nb * 128 + wn * 32 + nf * 8 + 2 * t4;
            float b0 = bias ? bias[colL] : 0.f;
            float b1 = bias ? bias[colL + 1] : 0.f;
            float v0 = c[mf][nf][0] + b0, v1 = c[mf][nf][1] + b1;
            float v2 = c[mf][nf][2] + b0, v3 = c[mf][nf][3] + b1;
            if (r0 < M)
                *(__half2*)(Cu + (size_t)r0 * N + colL) = __floats2half2_rn(v0, v1);
            if (r0 + 8 < M)
                *(__half2*)(Cu + (size_t)(r0 + 8) * N + colL) = __floats2half2_rn(v2, v3);
            if (STATS) {
                atomicAdd(&Ssum[colL], v0 + v2);
                atomicAdd(&Ssum[colL + 1], v1 + v3);
                atomicAdd(&Ssq[colL], fmaf(v0, v0, v2 * v2));
                atomicAdd(&Ssq[colL + 1], fmaf(v1, v1, v3 * v3));
            }
        }
    }
    if (STATS) {
        __syncthreads();
#pragma unroll
        for (int i = tid; i < NB * 128; i += THREADS) {
            atomicAdd(&g_sum[i], (double)Ssum[i]);
            atomicAdd(&g_sumsq[i], (double)Ssq[i]);
        }
    }
}

// ---------------- segment-reduce aggregations (8 ch/thread) ----------------
__global__ void k_agg_seg(const __half* __restrict__ H, __half* __restrict__ node, int logC) {
    const int sh = logC - 3;
    size_t tot = (size_t)NN << sh;
    for (size_t idx = (size_t)blockIdx.x * blockDim.x + threadIdx.x; idx < tot;
         idx += (size_t)gridDim.x * blockDim.x) {
        int n = (int)(idx >> sh);
        int cc = ((int)idx & ((1 << sh) - 1)) << 3;
        float4 al0 = *(const float4*)(g_alpha + cc);
        float4 al1 = *(const float4*)(g_alpha + cc + 4);
        float4 be0 = *(const float4*)(g_beta + cc);
        float4 be1 = *(const float4*)(g_beta + cc + 4);
        int p0 = g_seg[n], p1 = g_seg[n + 1];
        float s[8];
#pragma unroll
        for (int i = 0; i < 8; i++) s[i] = 0.f;
        for (int p = p0; p < p1; p++) {
            uint4 hv = *(const uint4*)(H + ((size_t)p << logC) + cc);
            float2 a;
            a = uf2(hv.x);
            s[0] += fmaxf(fmaf(al0.x, a.x, be0.x), 0.f);
            s[1] += fmaxf(fmaf(al0.y, a.y, be0.y), 0.f);
            a = uf2(hv.y);
            s[2] += fmaxf(fmaf(al0.z, a.x, be0.z), 0.f);
            s[3] += fmaxf(fmaf(al0.w, a.y, be0.w), 0.f);
            a = uf2(hv.z);
            s[4] += fmaxf(fmaf(al1.x, a.x, be1.x), 0.f);
            s[5] += fmaxf(fmaf(al1.y, a.y, be1.y), 0.f);
            a = uf2(hv.w);
            s[6] += fmaxf(fmaf(al1.z, a.x, be1.z), 0.f);
            s[7] += fmaxf(fmaf(al1.w, a.y, be1.w), 0.f);
        }
        float inv = g_invdeg[n];
        uint4 o;
        o.x = h2u(__floats2half2_rn(s[0] * inv, s[1] * inv));
        o.y = h2u(__floats2half2_rn(s[2] * inv, s[3] * inv));
        o.z = h2u(__floats2half2_rn(s[4] * inv, s[5] * inv));
        o.w = h2u(__floats2half2_rn(s[6] * inv, s[7] * inv));
        *(uint4*)(node + ((size_t)n << logC) + cc) = o;
    }
}

__global__ void k_agg_pq_seg(const __half* __restrict__ P, const __half* __restrict__ Qb,
                             const float* __restrict__ comb, __half* __restrict__ node) {
    size_t tot = (size_t)NN * 32;
    for (size_t idx = (size_t)blockIdx.x * blockDim.x + threadIdx.x; idx < tot;
         idx += (size_t)gridDim.x * blockDim.x) {
        int n = (int)(idx >> 5);
        int cc = ((int)idx & 31) << 3;
        float4 al0 = *(const float4*)(g_alpha + cc);
        float4 al1 = *(const float4*)(g_alpha + cc + 4);
        float4 be0 = *(const float4*)(g_beta + cc);
        float4 be1 = *(const float4*)(g_beta + cc + 4);
        float4 cb0 = *(const float4*)(comb + cc);
        float4 cb1 = *(const float4*)(comb + cc + 4);
        uint4 pv = *(const uint4*)(P + ((size_t)n << 8) + cc);
        float pb[8];
        {
            float2 a;
            a = uf2(pv.x); pb[0] = a.x + cb0.x; pb[1] = a.y + cb0.y;
            a = uf2(pv.y); pb[2] = a.x + cb0.z; pb[3] = a.y + cb0.w;
            a = uf2(pv.z); pb[4] = a.x + cb1.x; pb[5] = a.y + cb1.y;
            a = uf2(pv.w); pb[6] = a.x + cb1.z; pb[7] = a.y + cb1.w;
        }
        int p0 = g_seg[n], p1 = g_seg[n + 1];
        float s[8];
#pragma unroll
        for (int i = 0; i < 8; i++) s[i] = 0.f;
        for (int p = p0; p < p1; p++) {
            int sidx = g_ssrc[p];
            uint4 qv = *(const uint4*)(Qb + ((size_t)sidx << 8) + cc);
            float2 a;
            a = uf2(qv.x);
            s[0] += fmaxf(fmaf(al0.x, pb[0] + a.x, be0.x), 0.f);
            s[1] += fmaxf(fmaf(al0.y, pb[1] + a.y, be0.y), 0.f);
            a = uf2(qv.y);
            s[2] += fmaxf(fmaf(al0.z, pb[2] + a.x, be0.z), 0.f);
            s[3] += fmaxf(fmaf(al0.w, pb[3] + a.y, be0.w), 0.f);
            a = uf2(qv.z);
            s[4] += fmaxf(fmaf(al1.x, pb[4] + a.x, be1.x), 0.f);
            s[5] += fmaxf(fmaf(al1.y, pb[5] + a.y, be1.y), 0.f);
            a = uf2(qv.w);
            s[6] += fmaxf(fmaf(al1.z, pb[6] + a.x, be1.z), 0.f);
            s[7] += fmaxf(fmaf(al1.w, pb[7] + a.y, be1.w), 0.f);
        }
        float inv = g_invdeg[n];
        uint4 o;
        o.x = h2u(__floats2half2_rn(s[0] * inv, s[1] * inv));
        o.y = h2u(__floats2half2_rn(s[2] * inv, s[3] * inv));
        o.z = h2u(__floats2half2_rn(s[4] * inv, s[5] * inv));
        o.w = h2u(__floats2half2_rn(s[6] * inv, s[7] * inv));
        *(uint4*)(node + ((size_t)n << 8) + cc) = o;
    }
}

__global__ void k_pool_seg(const __half* __restrict__ h3) {
    int gph = blockIdx.x, t = threadIdx.x;
    int n0 = g_gseg[gph], n1 = g_gseg[gph + 1];
    float s = 0.f;
    for (int n = n0; n < n1; n++) s += __half2float(h3[(size_t)n * 256 + t]);
    g_pool[gph * 256 + t] = s / fmaxf((float)(n1 - n0), 1.f);
}

__global__ void k_head(const float* __restrict__ W1, const float* __restrict__ b1,
                       const float* __restrict__ W2, const float* __restrict__ b2,
                       float* __restrict__ out) {
    __shared__ float gv[256], hid[256], r0[256], r1[256];
    int r = blockIdx.x, t = threadIdx.x;
    gv[t] = g_pool[r * 256 + t];
    __syncthreads();
    float a = b1[t];
    for (int k = 0; k < 256; k++) a = fmaf(gv[k], W1[k * 256 + t], a);
    hid[t] = fmaxf(a, 0.f);
    __syncthreads();
    r0[t] = hid[t] * W2[t * 2 + 0];
    r1[t] = hid[t] * W2[t * 2 + 1];
    __syncthreads();
    for (int s = 128; s > 0; s >>= 1) {
        if (t < s) { r0[t] += r0[t + s]; r1[t] += r1[t + s]; }
        __syncthreads();
    }
    if (t == 0) {
        out[r * 2 + 0] = r0[0] + b2[0];
        out[r * 2 + 1] = r1[0] + b2[1];
    }
}

// ---------------- launcher ----------------
extern "C" void kernel_launch(void* const* d_in, const int* in_sizes, int n_in,
                              void* d_out, int out_size) {
    const float* x      = (const float*)d_in[0];
    const void*  ei     = d_in[1];
    const void*  bt     = d_in[2];
    const float* c1_w1  = (const float*)d_in[3];
    const float* c1_b1  = (const float*)d_in[4];
    const float* c1_gn1 = (const float*)d_in[5];
    const float* c1_w2  = (const float*)d_in[6];
    const float* c1_b2  = (const float*)d_in[7];
    const float* c1_gn2 = (const float*)d_in[8];
    const float* c1_w3  = (const float*)d_in[9];
    const float* c1_b3  = (const float*)d_in[10];
    const float* c1_gn3 = (const float*)d_in[11];
    const float* c2_w1  = (const float*)d_in[12];
    const float* c2_b1  = (const float*)d_in[13];
    const float* c2_gn1 = (const float*)d_in[14];
    const float* c2_w2  = (const float*)d_in[15];
    const float* c2_b2  = (const float*)d_in[16];
    const float* c2_gn2 = (const float*)d_in[17];
    const float* c3_w1  = (const float*)d_in[18];
    const float* c3_b1  = (const float*)d_in[19];
    const float* c3_gn1 = (const float*)d_in[20];
    const float* lw1    = (const float*)d_in[21];
    const float* lb1    = (const float*)d_in[22];
    const float* lw2    = (const float*)d_in[23];
    const float* lb2    = (const float*)d_in[24];
    float* out = (float*)d_out;
    (void)in_sizes; (void)n_in; (void)out_size;

    __half *pP, *pQ, *ph1, *ph2, *ph3, *pe0, *pe1;
    uint32_t *pwt, *pwtA, *pwtB;
    int *phist, *pdout, *pghist;
    cudaGetSymbolAddress((void**)&pP, g_P);
    cudaGetSymbolAddress((void**)&pQ, g_Q);
    cudaGetSymbolAddress((void**)&ph1, g_h1);
    cudaGetSymbolAddress((void**)&ph2, g_h2);
    cudaGetSymbolAddress((void**)&ph3, g_h3);
    cudaGetSymbolAddress((void**)&pe0, g_e0);
    cudaGetSymbolAddress((void**)&pe1, g_e1);
    cudaGetSymbolAddress((void**)&pwt, g_wtp);
    cudaGetSymbolAddress((void**)&pwtA, g_wtpA);
    cudaGetSymbolAddress((void**)&pwtB, g_wtpB);
    cudaGetSymbolAddress((void**)&phist, g_hist);
    cudaGetSymbolAddress((void**)&pdout, g_dout);
    cudaGetSymbolAddress((void**)&pghist, g_ghist);

    // setup
    cudaMemsetAsync(phist, 0, NN * sizeof(int));
    cudaMemsetAsync(pdout, 0, NN * sizeof(int));
    cudaMemsetAsync(pghist, 0, NG * sizeof(int));
    k_convert<<<1024, 256>>>(ei, bt);
    k_scan_nodes<<<1, 1024>>>();
    k_scan_graphs<<<1, 1024>>>();
    k_scatter<<<1024, 256>>>();

    const int ET128 = NE / 128;          // 128-row edge tiles (block 1)
    const int ET = NE / 64;              // 64-row edge tiles (block 2)
    const int NT = (NN + 63) / 64;

    // block 1 (C=128, 3 layers) — MW=4, 512 threads
    k_l1<<<2048, 128>>>(x, c1_w1);
    k_stats2<<<2048, 256>>>(pP, pQ, 7);
    k_finalize<<<1, 256>>>(c1_gn1, 128, c1_b1);
    k_trp<<<64, 256>>>(c1_w2, nullptr, pwt, 128, 128);
    wm_gemm<2, true, false, 1, 4, 512><<<ET128, 512>>>(pP, pQ, pwt, nullptr, c1_b2, c1_b1, pe0, nullptr, NE, 128);
    k_finalize<<<1, 256>>>(c1_gn2, 128, nullptr);
    k_trp<<<64, 256>>>(c1_w3, nullptr, pwtA, 128, 128);
    wm_gemm<1, true, false, 1, 4, 512><<<ET128, 512>>>(pe0, nullptr, pwtA, nullptr, c1_b3, nullptr, pe1, nullptr, NE, 128);
    k_finalize<<<1, 256>>>(c1_gn3, 128, nullptr);
    k_agg_seg<<<4096, 256>>>(pe1, ph1, 7);

    // block 2 (C=256, 2 layers) — NB=2, MW=2, 512 threads
    k_trp<<<128, 256>>>(c2_w1, c2_w1 + 128 * 256, pwtA, 128, 256);
    k_trp<<<128, 256>>>(c2_w1 + 128 * 256, nullptr, pwtB, 128, 256);
    wm_gemm<0, false, true, 2, 2, 512><<<dim3(NT, 2), 512>>>(ph1, nullptr, pwtA, pwtB, nullptr, nullptr, pP, pQ, NN, 128);
    k_stats2<<<2048, 256>>>(pP, pQ, 8);
    k_finalize<<<1, 256>>>(c2_gn1, 256, c2_b1);
    k_trp<<<256, 256>>>(c2_w2, nullptr, pwt, 256, 256);
    wm_gemm<2, true, false, 2, 2, 512><<<ET, 512>>>(pP, pQ, pwt, nullptr, c2_b2, c2_b1, pe0, nullptr, NE, 256);
    k_finalize<<<1, 256>>>(c2_gn2, 256, nullptr);
    k_agg_seg<<<8192, 256>>>(pe0, ph2, 8);

    // block 3 (C=256, 1 layer — no edge GEMM)
    k_trp<<<256, 256>>>(c3_w1, c3_w1 + 256 * 256, pwtA, 256, 256);
    k_trp<<<256, 256>>>(c3_w1 + 256 * 256, nullptr, pwtB, 256, 256);
    wm_gemm<0, false, true, 2, 2, 512><<<dim3(NT, 2), 512>>>(ph2, nullptr, pwtA, pwtB, nullptr, nullptr, pP, pQ, NN, 256);
    k_stats2<<<2048, 256>>>(pP, pQ, 8);
    k_finalize<<<1, 256>>>(c3_gn1, 256, c3_b1);
    k_agg_pq_seg<<<4096, 256>>>(pP, pQ, c3_b1, ph3);

    // pool + head
    k_pool_seg<<<NG, 256>>>(ph3);
    k_head<<<NG, 256>>>(lw1, lb1, lw2, lb2, out);
}